// round 8
// baseline (speedup 1.0000x reference)
#include <cuda_runtime.h>
#include <math.h>

#define N_NODES 10000
#define N_EDGES 320000
#define E2      (N_EDGES + N_NODES)   // + self loops
#define IN_CH   512
#define D1      512                   // HEADS * HID
#define HEADS   4
#define HID     128
#define NEG_SLOPE 0.2f

// ---------------- scratch (no allocations allowed) ----------------
__device__ __align__(16) float g_h1  [N_NODES * D1];   // x @ W1
__device__ __align__(16) float g_act1[N_NODES * D1];   // elu(agg1 + b1)
__device__ float g_asrc1[N_NODES * HEADS];
__device__ float g_adst1[N_NODES * HEADS];
__device__ __align__(16) float g_h2[N_NODES * 2];
__device__ float g_asrc2[N_NODES];
__device__ float g_adst2[N_NODES];
__device__ int g_deg[N_NODES];
__device__ int g_row[N_NODES + 1];
__device__ int g_cur[N_NODES];
__device__ int g_csr[E2];

// ---------------- helpers ----------------
__device__ __forceinline__ float lrelu(float e) { return e > 0.f ? e : NEG_SLOPE * e; }

// packed f32x2 FMA: d = a*b + d (lane-wise on 2 packed floats). 2x fp32 tput.
__device__ __forceinline__ void ffma2(unsigned long long& d, unsigned long long a,
                                      unsigned long long b) {
    asm("fma.rn.f32x2 %0, %1, %2, %0;" : "+l"(d) : "l"(a), "l"(b));
}
__device__ __forceinline__ float2 unpk(unsigned long long v) {
    float2 r;
    asm("mov.b64 {%0, %1}, %2;" : "=f"(r.x), "=f"(r.y) : "l"(v));
    return r;
}

// ---------------- kernel: zero degree histogram ----------------
__global__ void k_zero() {
    int i = blockIdx.x * blockDim.x + threadIdx.x;
    if (i < N_NODES) g_deg[i] = 0;
}

// ---------------- kernel: GEMM1  h1 = x @ W1  (M=10000, N=512, K=512) ------------
// 128x64 tile, BK=8, double-buffered smem, 128 threads, 8x8 per thread via FFMA2.
// A tile stored DUPLICATED in smem: float index 2m and 2m+1 both hold A[m][k],
// so each u64 smem word is (a,a) ready for fma.rn.f32x2 with no packing MOVs.
#define GBM 128
#define GBN 64
#define GBK 8
#define NKT (IN_CH / GBK)  // 64 stages

__global__ __launch_bounds__(128, 4) void k_gemm1(const float* __restrict__ A,
                                                  const float* __restrict__ B) {
    __shared__ float As[2][GBK][GBM * 2];  // 16 KB (duplicated)
    __shared__ float Bs[2][GBK][GBN];      // 4 KB
    const int bm = blockIdx.x * GBM;
    const int bn = blockIdx.y * GBN;
    const int tid = threadIdx.x;
    const int tx = tid & 7;   // 8 col groups of 8
    const int ty = tid >> 3;  // 16 row groups of 8

    // A loader: 128 rows x 8 k = 256 float4 -> 2 per thread (rows ar0, ar0+64)
    const int ar0 = tid >> 1;
    const int ak0 = (tid & 1) * 4;
    // B loader: 8 rows x 64 cols = 128 float4 -> 1 per thread
    const int br = tid >> 4;
    const int bc = (tid & 15) * 4;

    int rowA0 = bm + ar0;       if (rowA0 >= N_NODES) rowA0 = N_NODES - 1;  // clamp (stores guarded)
    int rowA1 = bm + ar0 + 64;  if (rowA1 >= N_NODES) rowA1 = N_NODES - 1;
    const float* Ap0 = A + (size_t)rowA0 * IN_CH + ak0;
    const float* Ap1 = A + (size_t)rowA1 * IN_CH + ak0;
    const float* Bp  = B + (size_t)br * D1 + bn + bc;

    unsigned long long acc[8][4];
#pragma unroll
    for (int i = 0; i < 8; i++)
#pragma unroll
        for (int j = 0; j < 4; j++) acc[i][j] = 0ULL;

    // prologue: stage 0
    float4 a0 = *(const float4*)(Ap0);
    float4 a1 = *(const float4*)(Ap1);
    float4 b0 = *(const float4*)(Bp);
    {
        *(float2*)&As[0][ak0 + 0][2 * ar0] = make_float2(a0.x, a0.x);
        *(float2*)&As[0][ak0 + 1][2 * ar0] = make_float2(a0.y, a0.y);
        *(float2*)&As[0][ak0 + 2][2 * ar0] = make_float2(a0.z, a0.z);
        *(float2*)&As[0][ak0 + 3][2 * ar0] = make_float2(a0.w, a0.w);
        *(float2*)&As[0][ak0 + 0][2 * (ar0 + 64)] = make_float2(a1.x, a1.x);
        *(float2*)&As[0][ak0 + 1][2 * (ar0 + 64)] = make_float2(a1.y, a1.y);
        *(float2*)&As[0][ak0 + 2][2 * (ar0 + 64)] = make_float2(a1.z, a1.z);
        *(float2*)&As[0][ak0 + 3][2 * (ar0 + 64)] = make_float2(a1.w, a1.w);
        *(float4*)&Bs[0][br][bc] = b0;
    }
    __syncthreads();

    int buf = 0;
    for (int t = 0; t < NKT; t++) {
        float4 na0, na1, nb0;
        if (t + 1 < NKT) {
            const int k0 = (t + 1) * GBK;
            na0 = *(const float4*)(Ap0 + k0);
            na1 = *(const float4*)(Ap1 + k0);
            nb0 = *(const float4*)(Bp + (size_t)k0 * D1);
        }
#pragma unroll
        for (int kk = 0; kk < GBK; kk++) {
            ulonglong2 av0 = *(const ulonglong2*)&As[buf][kk][ty * 16];       // rows 0,1
            ulonglong2 av1 = *(const ulonglong2*)&As[buf][kk][ty * 16 + 4];   // rows 2,3
            ulonglong2 av2 = *(const ulonglong2*)&As[buf][kk][ty * 16 + 8];   // rows 4,5
            ulonglong2 av3 = *(const ulonglong2*)&As[buf][kk][ty * 16 + 12];  // rows 6,7
            ulonglong2 bv0 = *(const ulonglong2*)&Bs[buf][kk][tx * 8];        // cols 0-3
            ulonglong2 bv1 = *(const ulonglong2*)&Bs[buf][kk][tx * 8 + 4];    // cols 4-7
            unsigned long long bb0 = bv0.x, bb1 = bv0.y, bb2 = bv1.x, bb3 = bv1.y;
            ffma2(acc[0][0], av0.x, bb0); ffma2(acc[0][1], av0.x, bb1);
            ffma2(acc[0][2], av0.x, bb2); ffma2(acc[0][3], av0.x, bb3);
            ffma2(acc[1][0], av0.y, bb0); ffma2(acc[1][1], av0.y, bb1);
            ffma2(acc[1][2], av0.y, bb2); ffma2(acc[1][3], av0.y, bb3);
            ffma2(acc[2][0], av1.x, bb0); ffma2(acc[2][1], av1.x, bb1);
            ffma2(acc[2][2], av1.x, bb2); ffma2(acc[2][3], av1.x, bb3);
            ffma2(acc[3][0], av1.y, bb0); ffma2(acc[3][1], av1.y, bb1);
            ffma2(acc[3][2], av1.y, bb2); ffma2(acc[3][3], av1.y, bb3);
            ffma2(acc[4][0], av2.x, bb0); ffma2(acc[4][1], av2.x, bb1);
            ffma2(acc[4][2], av2.x, bb2); ffma2(acc[4][3], av2.x, bb3);
            ffma2(acc[5][0], av2.y, bb0); ffma2(acc[5][1], av2.y, bb1);
            ffma2(acc[5][2], av2.y, bb2); ffma2(acc[5][3], av2.y, bb3);
            ffma2(acc[6][0], av3.x, bb0); ffma2(acc[6][1], av3.x, bb1);
            ffma2(acc[6][2], av3.x, bb2); ffma2(acc[6][3], av3.x, bb3);
            ffma2(acc[7][0], av3.y, bb0); ffma2(acc[7][1], av3.y, bb1);
            ffma2(acc[7][2], av3.y, bb2); ffma2(acc[7][3], av3.y, bb3);
        }
        if (t + 1 < NKT) {
            const int nb = buf ^ 1;
            *(float2*)&As[nb][ak0 + 0][2 * ar0] = make_float2(na0.x, na0.x);
            *(float2*)&As[nb][ak0 + 1][2 * ar0] = make_float2(na0.y, na0.y);
            *(float2*)&As[nb][ak0 + 2][2 * ar0] = make_float2(na0.z, na0.z);
            *(float2*)&As[nb][ak0 + 3][2 * ar0] = make_float2(na0.w, na0.w);
            *(float2*)&As[nb][ak0 + 0][2 * (ar0 + 64)] = make_float2(na1.x, na1.x);
            *(float2*)&As[nb][ak0 + 1][2 * (ar0 + 64)] = make_float2(na1.y, na1.y);
            *(float2*)&As[nb][ak0 + 2][2 * (ar0 + 64)] = make_float2(na1.z, na1.z);
            *(float2*)&As[nb][ak0 + 3][2 * (ar0 + 64)] = make_float2(na1.w, na1.w);
            *(float4*)&Bs[nb][br][bc] = nb0;
            __syncthreads();
            buf = nb;
        }
    }

    // epilogue: rows ty*8+i, cols bn + tx*8 .. +7
#pragma unroll
    for (int i = 0; i < 8; i++) {
        const int row = bm + ty * 8 + i;
        if (row < N_NODES) {
            float2 c0 = unpk(acc[i][0]), c1 = unpk(acc[i][1]);
            float2 c2 = unpk(acc[i][2]), c3 = unpk(acc[i][3]);
            float* dst = g_h1 + (size_t)row * D1 + bn + tx * 8;
            *(float4*)dst = make_float4(c0.x, c0.y, c1.x, c1.y);
            *(float4*)(dst + 4) = make_float4(c2.x, c2.y, c3.x, c3.y);
        }
    }
}

// ---------------- kernel: per-node attention scalars a_src1/a_dst1 ----------------
__global__ void k_att1(const float* __restrict__ as1, const float* __restrict__ ad1) {
    int n = blockIdx.x;
    int h = threadIdx.x >> 5;
    int lane = threadIdx.x & 31;
    float4 hv = ((const float4*)g_h1)[(size_t)n * 128 + h * 32 + lane];
    float4 sa = ((const float4*)as1)[h * 32 + lane];
    float4 da = ((const float4*)ad1)[h * 32 + lane];
    float s = hv.x * sa.x + hv.y * sa.y + hv.z * sa.z + hv.w * sa.w;
    float d = hv.x * da.x + hv.y * da.y + hv.z * da.z + hv.w * da.w;
#pragma unroll
    for (int o = 16; o > 0; o >>= 1) {
        s += __shfl_xor_sync(0xffffffffu, s, o);
        d += __shfl_xor_sync(0xffffffffu, d, o);
    }
    if (lane == 0) {
        g_asrc1[n * HEADS + h] = s;
        g_adst1[n * HEADS + h] = d;
    }
}

// ---------------- CSR build: histogram / scan / scatter ----------------
__global__ void k_hist(const int* __restrict__ ei) {
    int e = blockIdx.x * blockDim.x + threadIdx.x;
    if (e >= E2) return;
    int dst = (e < N_EDGES) ? ei[N_EDGES + e] : (e - N_EDGES);
    atomicAdd(&g_deg[dst], 1);
}

__global__ void k_scan() {
    __shared__ int part[1024];
    const int tid = threadIdx.x;
    const int CH = (N_NODES + 1023) / 1024;  // 10
    int base = tid * CH;
    int s = 0;
    for (int i = 0; i < CH; i++) {
        int idx = base + i;
        if (idx < N_NODES) s += g_deg[idx];
    }
    part[tid] = s;
    __syncthreads();
    for (int off = 1; off < 1024; off <<= 1) {
        int v = (tid >= off) ? part[tid - off] : 0;
        __syncthreads();
        part[tid] += v;
        __syncthreads();
    }
    int run = (tid == 0) ? 0 : part[tid - 1];
    for (int i = 0; i < CH; i++) {
        int idx = base + i;
        if (idx < N_NODES) {
            g_row[idx] = run;
            g_cur[idx] = run;
            run += g_deg[idx];
        }
    }
    if (tid == 1023) g_row[N_NODES] = part[1023];
}

__global__ void k_scatter(const int* __restrict__ ei) {
    int e = blockIdx.x * blockDim.x + threadIdx.x;
    if (e >= E2) return;
    int src, dst;
    if (e < N_EDGES) {
        src = ei[e];
        dst = ei[N_EDGES + e];
    } else {
        src = dst = e - N_EDGES;
    }
    int p = atomicAdd(&g_cur[dst], 1);
    g_csr[p] = src;
}

// ---------------- kernel: layer-1 softmax-aggregate + bias + ELU ----------------
// one 128-thread CTA per dst node; thread t owns channels [4t, 4t+4); head = t/32.
__global__ __launch_bounds__(128) void k_agg1(const float* __restrict__ b1) {
    const int n = blockIdx.x;
    const int tid = threadIdx.x;
    __shared__ float4 red[128];
    __shared__ float s_ad[4];
    if (tid < 4) s_ad[tid] = g_adst1[n * HEADS + tid];
    __syncthreads();
    const int beg = g_row[n];
    const int end = g_row[n + 1];
    const float a0 = s_ad[0], a1 = s_ad[1], a2 = s_ad[2], a3 = s_ad[3];

    // pass A: per-head max over incoming edges
    float4 mx = make_float4(-INFINITY, -INFINITY, -INFINITY, -INFINITY);
    for (int k = beg + tid; k < end; k += 128) {
        int s = g_csr[k];
        const float* as = &g_asrc1[s * HEADS];
        mx.x = fmaxf(mx.x, lrelu(as[0] + a0));
        mx.y = fmaxf(mx.y, lrelu(as[1] + a1));
        mx.z = fmaxf(mx.z, lrelu(as[2] + a2));
        mx.w = fmaxf(mx.w, lrelu(as[3] + a3));
    }
    red[tid] = mx;
    __syncthreads();
#pragma unroll
    for (int off = 64; off > 0; off >>= 1) {
        if (tid < off) {
            float4 u = red[tid], v = red[tid + off];
            u.x = fmaxf(u.x, v.x);
            u.y = fmaxf(u.y, v.y);
            u.z = fmaxf(u.z, v.z);
            u.w = fmaxf(u.w, v.w);
            red[tid] = u;
        }
        __syncthreads();
    }
    const float4 M4 = red[0];

    const int h = tid >> 5;
    const float mh = (h == 0) ? M4.x : (h == 1) ? M4.y : (h == 2) ? M4.z : M4.w;
    const float ah = (h == 0) ? a0 : (h == 1) ? a1 : (h == 2) ? a2 : a3;

    // pass B: every thread walks all edges; unnormalized accumulate + own denominator
    const float4* h1v = (const float4*)g_h1;
    float4 acc = make_float4(0.f, 0.f, 0.f, 0.f);
    float den = 0.f;
    for (int k = beg; k < end; k++) {
        int s = g_csr[k];  // broadcast load
        float e = lrelu(g_asrc1[s * HEADS + h] + ah);
        float ex = expf(e - mh);
        den += ex;
        float4 hv = h1v[(size_t)s * 128 + tid];
        acc.x = fmaf(ex, hv.x, acc.x);
        acc.y = fmaf(ex, hv.y, acc.y);
        acc.z = fmaf(ex, hv.z, acc.z);
        acc.w = fmaf(ex, hv.w, acc.w);
    }
    const float inv = 1.f / (den + 1e-16f);
    float4 bb = ((const float4*)b1)[tid];
    float o0 = acc.x * inv + bb.x;
    float o1 = acc.y * inv + bb.y;
    float o2 = acc.z * inv + bb.z;
    float o3 = acc.w * inv + bb.w;
    // ELU (alpha=1)
    o0 = o0 > 0.f ? o0 : expm1f(o0);
    o1 = o1 > 0.f ? o1 : expm1f(o1);
    o2 = o2 > 0.f ? o2 : expm1f(o2);
    o3 = o3 > 0.f ? o3 : expm1f(o3);
    ((float4*)g_act1)[(size_t)n * 128 + tid] = make_float4(o0, o1, o2, o3);
}

// ---------------- kernel: layer-2 GEMV (512->2) + attention scalars ----------------
__global__ __launch_bounds__(128) void k_l2(const float* __restrict__ W2,
                                            const float* __restrict__ as2,
                                            const float* __restrict__ ad2) {
    const int n = blockIdx.x;
    const int tid = threadIdx.x;
    __shared__ float2 red[128];
    float4 a = ((const float4*)g_act1)[(size_t)n * 128 + tid];
    float4 w01 = ((const float4*)W2)[tid * 2];
    float4 w23 = ((const float4*)W2)[tid * 2 + 1];
    float s0 = a.x * w01.x + a.y * w01.z + a.z * w23.x + a.w * w23.z;
    float s1 = a.x * w01.y + a.y * w01.w + a.z * w23.y + a.w * w23.w;
    red[tid] = make_float2(s0, s1);
    __syncthreads();
#pragma unroll
    for (int off = 64; off > 0; off >>= 1) {
        if (tid < off) {
            red[tid].x += red[tid + off].x;
            red[tid].y += red[tid + off].y;
        }
        __syncthreads();
    }
    if (tid == 0) {
        float h0 = red[0].x, h1 = red[0].y;
        g_h2[n * 2] = h0;
        g_h2[n * 2 + 1] = h1;
        g_asrc2[n] = h0 * as2[0] + h1 * as2[1];
        g_adst2[n] = h0 * ad2[0] + h1 * ad2[1];
    }
}

// ---------------- kernel: layer-2 aggregate (one warp per node) ----------------
__global__ __launch_bounds__(128) void k_agg2(const float* __restrict__ b2,
                                              float* __restrict__ out) {
    const int warp = threadIdx.x >> 5;
    const int lane = threadIdx.x & 31;
    const int n = blockIdx.x * 4 + warp;
    if (n >= N_NODES) return;
    const int beg = g_row[n];
    const int end = g_row[n + 1];
    const float ad = g_adst2[n];

    float mx = -INFINITY;
    for (int k = beg + lane; k < end; k += 32)
        mx = fmaxf(mx, lrelu(g_asrc2[g_csr[k]] + ad));
#pragma unroll
    for (int o = 16; o > 0; o >>= 1) mx = fmaxf(mx, __shfl_xor_sync(0xffffffffu, mx, o));

    float den = 0.f, c0 = 0.f, c1 = 0.f;
    for (int k = beg + lane; k < end; k += 32) {
        int s = g_csr[k];
        float e = lrelu(g_asrc2[s] + ad);
        float ex = expf(e - mx);
        den += ex;
        float2 hv = ((const float2*)g_h2)[s];
        c0 = fmaf(ex, hv.x, c0);
        c1 = fmaf(ex, hv.y, c1);
    }
#pragma unroll
    for (int o = 16; o > 0; o >>= 1) {
        den += __shfl_xor_sync(0xffffffffu, den, o);
        c0 += __shfl_xor_sync(0xffffffffu, c0, o);
        c1 += __shfl_xor_sync(0xffffffffu, c1, o);
    }
    if (lane == 0) {
        float inv = 1.f / (den + 1e-16f);
        out[n * 2] = c0 * inv + b2[0];
        out[n * 2 + 1] = c1 * inv + b2[1];
    }
}

// ---------------- launch (single stream; isolate FFMA2 GEMM change) ----------------
extern "C" void kernel_launch(void* const* d_in, const int* in_sizes, int n_in,
                              void* d_out, int out_size) {
    const float* x   = (const float*)d_in[0];
    const int*   ei  = (const int*)d_in[1];
    const float* W1  = (const float*)d_in[2];
    const float* as1 = (const float*)d_in[3];
    const float* ad1 = (const float*)d_in[4];
    const float* b1  = (const float*)d_in[5];
    const float* W2  = (const float*)d_in[6];
    const float* as2 = (const float*)d_in[7];
    const float* ad2 = (const float*)d_in[8];
    const float* b2  = (const float*)d_in[9];
    float* out = (float*)d_out;

    k_zero<<<(N_NODES + 255) / 256, 256>>>();
    k_gemm1<<<dim3((N_NODES + GBM - 1) / GBM, D1 / GBN), 128>>>(x, W1);
    k_att1<<<N_NODES, 128>>>(as1, ad1);
    k_hist<<<(E2 + 255) / 256, 256>>>(ei);
    k_scan<<<1, 1024>>>();
    k_scatter<<<(E2 + 255) / 256, 256>>>(ei);
    k_agg1<<<N_NODES, 128>>>(b1);
    k_l2<<<N_NODES, 128>>>(W2, as2, ad2);
    k_agg2<<<(N_NODES + 3) / 4, 128>>>(b2, out);
}

// round 10
// speedup vs baseline: 1.2668x; 1.2668x over previous
#include <cuda_runtime.h>
#include <cuda_bf16.h>
#include <math.h>
#include <stdint.h>

#define N_NODES 10000
#define N_EDGES 320000
#define E2      (N_EDGES + N_NODES)   // + self loops
#define IN_CH   512
#define D1      512                   // HEADS * HID
#define HEADS   4
#define HID     128
#define NEG_SLOPE 0.2f
#define KBIG    1536                  // 3 * 512 (split-K trick)

// ---------------- scratch (no allocations allowed) ----------------
__device__ __align__(16) float g_h1  [N_NODES * D1];   // x @ W1 (fp32 result)
__device__ __align__(16) float g_act1[N_NODES * D1];   // elu(agg1 + b1)
__device__ float g_asrc1[N_NODES * HEADS];
__device__ float g_adst1[N_NODES * HEADS];
__device__ __align__(16) float g_h2[N_NODES * 2];
__device__ float g_asrc2[N_NODES];
__device__ float g_adst2[N_NODES];
__device__ int g_deg[N_NODES];
__device__ int g_row[N_NODES + 1];
__device__ int g_cur[N_NODES];
__device__ int g_csr[E2];
// split operands: A' = [ah | ah | al] (rows=M, K'=1536), B' = [bh | bl | bh] (rows=N=512)
__device__ __align__(16) unsigned short g_Abig[(size_t)N_NODES * KBIG];  // 30.7 MB bf16
__device__ __align__(16) unsigned short g_Bbig[(size_t)D1 * KBIG];      // 1.6 MB bf16

// ---------------- helpers ----------------
__device__ __forceinline__ float lrelu(float e) { return e > 0.f ? e : NEG_SLOPE * e; }

__device__ __forceinline__ unsigned short f2bf(float f) {
    __nv_bfloat16 b = __float2bfloat16(f);
    return *reinterpret_cast<unsigned short*>(&b);
}
__device__ __forceinline__ float bf2f(unsigned short u) {
    __nv_bfloat16 b;
    *reinterpret_cast<unsigned short*>(&b) = u;
    return __bfloat162float(b);
}

// ---------------- kernel: zero degree histogram ----------------
__global__ void k_zero() {
    int i = blockIdx.x * blockDim.x + threadIdx.x;
    if (i < N_NODES) g_deg[i] = 0;
}

// ---------------- split kernels: build A' and B' ----------------
__global__ __launch_bounds__(256) void k_split_a(const float* __restrict__ x) {
    int t = blockIdx.x * blockDim.x + threadIdx.x;  // N_NODES*128 threads, 4 elems each
    if (t >= N_NODES * 128) return;
    int m = t >> 7;
    int k4 = (t & 127) * 4;
    float4 v = *(const float4*)(x + (size_t)m * IN_CH + k4);
    unsigned short h0 = f2bf(v.x), h1 = f2bf(v.y), h2 = f2bf(v.z), h3 = f2bf(v.w);
    unsigned short l0 = f2bf(v.x - bf2f(h0)), l1 = f2bf(v.y - bf2f(h1));
    unsigned short l2 = f2bf(v.z - bf2f(h2)), l3 = f2bf(v.w - bf2f(h3));
    uint2 hi2 = make_uint2((uint32_t)h0 | ((uint32_t)h1 << 16),
                           (uint32_t)h2 | ((uint32_t)h3 << 16));
    uint2 lo2 = make_uint2((uint32_t)l0 | ((uint32_t)l1 << 16),
                           (uint32_t)l2 | ((uint32_t)l3 << 16));
    size_t base = (size_t)m * KBIG;
    *(uint2*)(g_Abig + base + k4) = hi2;          // ah
    *(uint2*)(g_Abig + base + 512 + k4) = hi2;    // ah
    *(uint2*)(g_Abig + base + 1024 + k4) = lo2;   // al
}

__global__ __launch_bounds__(256) void k_split_b(const float* __restrict__ W1) {
    int t = blockIdx.x * blockDim.x + threadIdx.x;  // 512*512
    if (t >= IN_CH * D1) return;
    int k = t >> 9;     // row of W1
    int n = t & 511;    // col of W1 -> row of B'
    float w = W1[(size_t)k * D1 + n];
    unsigned short h = f2bf(w);
    unsigned short l = f2bf(w - bf2f(h));
    size_t base = (size_t)n * KBIG;
    g_Bbig[base + k] = h;           // bh
    g_Bbig[base + 512 + k] = l;     // bl
    g_Bbig[base + 1024 + k] = h;    // bh
}

// ---------------- kernel: mma.sync bf16 GEMM  g_h1 = A' @ B'^T ----------------
// 128x128 CTA tile, 8 warps (2x4 -> 64x32 warp tile), BK=32, double-buffered.
// mma.sync.aligned.m16n8k16.row.col.f32.bf16.bf16.f32 (base-ISA; HMMA on sm_103).
#define TBM 128
#define TBN 128
#define TBK 32
#define TNC (KBIG / TBK)     // 48 chunks
#define ASTR (TBK + 8)       // 40 shorts/row: g-stride = 20 banks -> conflict-free

__device__ __forceinline__ void mma16816(float* c, const uint32_t* a, const uint32_t* b) {
    asm volatile(
        "mma.sync.aligned.m16n8k16.row.col.f32.bf16.bf16.f32 "
        "{%0,%1,%2,%3}, {%4,%5,%6,%7}, {%8,%9}, {%0,%1,%2,%3};"
        : "+f"(c[0]), "+f"(c[1]), "+f"(c[2]), "+f"(c[3])
        : "r"(a[0]), "r"(a[1]), "r"(a[2]), "r"(a[3]), "r"(b[0]), "r"(b[1]));
}

__global__ __launch_bounds__(256) void k_gemm_mma() {
    __shared__ unsigned short As[2][TBM][ASTR];
    __shared__ unsigned short Bs[2][TBN][ASTR];
    const int tid = threadIdx.x;
    const int wid = tid >> 5;
    const int lane = tid & 31;
    const int g = lane >> 2;   // 0..7
    const int tg = lane & 3;   // 0..3
    const int wm = (wid & 1) * 64;
    const int wn = (wid >> 1) * 32;
    const int bm = blockIdx.x * TBM;
    const int bn = blockIdx.y * TBN;

    // loaders: per tile 128 rows x 32 shorts = 512 x 16B; 2 segs/thread
    const int lr0 = tid >> 1;            // rows tid/2 and tid/2+... use s = tid + i*256
    (void)lr0;
    int garow[2], gbrow[2], lrow[2], lq[2];
#pragma unroll
    for (int i = 0; i < 2; i++) {
        int s = tid + i * 256;
        lrow[i] = s >> 2;
        lq[i] = (s & 3) * 8;  // short offset of 16B seg
        int gm = bm + lrow[i];
        garow[i] = (gm < N_NODES) ? gm : (N_NODES - 1);
        gbrow[i] = bn + lrow[i];  // < 512 always
    }

    float acc[4][4][4];
#pragma unroll
    for (int mi = 0; mi < 4; mi++)
#pragma unroll
        for (int ni = 0; ni < 4; ni++)
#pragma unroll
            for (int j = 0; j < 4; j++) acc[mi][ni][j] = 0.f;

    uint4 pa[2], pb[2];
#pragma unroll
    for (int i = 0; i < 2; i++) {
        pa[i] = *(const uint4*)(g_Abig + (size_t)garow[i] * KBIG + lq[i]);
        pb[i] = *(const uint4*)(g_Bbig + (size_t)gbrow[i] * KBIG + lq[i]);
    }
#pragma unroll
    for (int i = 0; i < 2; i++) {
        *(uint4*)&As[0][lrow[i]][lq[i]] = pa[i];
        *(uint4*)&Bs[0][lrow[i]][lq[i]] = pb[i];
    }
    __syncthreads();

    for (int c = 0; c < TNC; c++) {
        const int b = c & 1;
        if (c + 1 < TNC) {
            const int k0 = (c + 1) * TBK;
#pragma unroll
            for (int i = 0; i < 2; i++) {
                pa[i] = *(const uint4*)(g_Abig + (size_t)garow[i] * KBIG + k0 + lq[i]);
                pb[i] = *(const uint4*)(g_Bbig + (size_t)gbrow[i] * KBIG + k0 + lq[i]);
            }
        }
#pragma unroll
        for (int ks = 0; ks < 2; ks++) {
            const int kb = ks * 16;
            uint32_t af[4][4], bf[4][2];
#pragma unroll
            for (int mi = 0; mi < 4; mi++) {
                const int r = wm + mi * 16 + g;
                af[mi][0] = *(const uint32_t*)&As[b][r][kb + tg * 2];
                af[mi][1] = *(const uint32_t*)&As[b][r + 8][kb + tg * 2];
                af[mi][2] = *(const uint32_t*)&As[b][r][kb + tg * 2 + 8];
                af[mi][3] = *(const uint32_t*)&As[b][r + 8][kb + tg * 2 + 8];
            }
#pragma unroll
            for (int ni = 0; ni < 4; ni++) {
                const int n = wn + ni * 8 + g;
                bf[ni][0] = *(const uint32_t*)&Bs[b][n][kb + tg * 2];
                bf[ni][1] = *(const uint32_t*)&Bs[b][n][kb + tg * 2 + 8];
            }
#pragma unroll
            for (int mi = 0; mi < 4; mi++)
#pragma unroll
                for (int ni = 0; ni < 4; ni++) mma16816(acc[mi][ni], af[mi], bf[ni]);
        }
        if (c + 1 < TNC) {
            const int nb = b ^ 1;
#pragma unroll
            for (int i = 0; i < 2; i++) {
                *(uint4*)&As[nb][lrow[i]][lq[i]] = pa[i];
                *(uint4*)&Bs[nb][lrow[i]][lq[i]] = pb[i];
            }
            __syncthreads();
        }
    }

    // epilogue: frag (mi,ni): c0,c1 -> (row, col..col+1), c2,c3 -> (row+8, ...)
#pragma unroll
    for (int mi = 0; mi < 4; mi++) {
        const int r0 = bm + wm + mi * 16 + g;
#pragma unroll
        for (int ni = 0; ni < 4; ni++) {
            const int col = bn + wn + ni * 8 + tg * 2;
            if (r0 < N_NODES)
                *(float2*)(g_h1 + (size_t)r0 * D1 + col) = make_float2(acc[mi][ni][0], acc[mi][ni][1]);
            if (r0 + 8 < N_NODES)
                *(float2*)(g_h1 + (size_t)(r0 + 8) * D1 + col) = make_float2(acc[mi][ni][2], acc[mi][ni][3]);
        }
    }
}

// ---------------- kernel: per-node attention scalars a_src1/a_dst1 ----------------
__global__ void k_att1(const float* __restrict__ as1, const float* __restrict__ ad1) {
    int n = blockIdx.x;
    int h = threadIdx.x >> 5;
    int lane = threadIdx.x & 31;
    float4 hv = ((const float4*)g_h1)[(size_t)n * 128 + h * 32 + lane];
    float4 sa = ((const float4*)as1)[h * 32 + lane];
    float4 da = ((const float4*)ad1)[h * 32 + lane];
    float s = hv.x * sa.x + hv.y * sa.y + hv.z * sa.z + hv.w * sa.w;
    float d = hv.x * da.x + hv.y * da.y + hv.z * da.z + hv.w * da.w;
#pragma unroll
    for (int o = 16; o > 0; o >>= 1) {
        s += __shfl_xor_sync(0xffffffffu, s, o);
        d += __shfl_xor_sync(0xffffffffu, d, o);
    }
    if (lane == 0) {
        g_asrc1[n * HEADS + h] = s;
        g_adst1[n * HEADS + h] = d;
    }
}

// ---------------- CSR build: histogram / scan / scatter ----------------
__global__ void k_hist(const int* __restrict__ ei) {
    int e = blockIdx.x * blockDim.x + threadIdx.x;
    if (e >= E2) return;
    int dst = (e < N_EDGES) ? ei[N_EDGES + e] : (e - N_EDGES);
    atomicAdd(&g_deg[dst], 1);
}

__global__ void k_scan() {
    __shared__ int part[1024];
    const int tid = threadIdx.x;
    const int CH = (N_NODES + 1023) / 1024;  // 10
    int base = tid * CH;
    int s = 0;
    for (int i = 0; i < CH; i++) {
        int idx = base + i;
        if (idx < N_NODES) s += g_deg[idx];
    }
    part[tid] = s;
    __syncthreads();
    for (int off = 1; off < 1024; off <<= 1) {
        int v = (tid >= off) ? part[tid - off] : 0;
        __syncthreads();
        part[tid] += v;
        __syncthreads();
    }
    int run = (tid == 0) ? 0 : part[tid - 1];
    for (int i = 0; i < CH; i++) {
        int idx = base + i;
        if (idx < N_NODES) {
            g_row[idx] = run;
            g_cur[idx] = run;
            run += g_deg[idx];
        }
    }
    if (tid == 1023) g_row[N_NODES] = part[1023];
}

__global__ void k_scatter(const int* __restrict__ ei) {
    int e = blockIdx.x * blockDim.x + threadIdx.x;
    if (e >= E2) return;
    int src, dst;
    if (e < N_EDGES) {
        src = ei[e];
        dst = ei[N_EDGES + e];
    } else {
        src = dst = e - N_EDGES;
    }
    int p = atomicAdd(&g_cur[dst], 1);
    g_csr[p] = src;
}

// ---------------- kernel: layer-1 softmax-aggregate + bias + ELU ----------------
__global__ __launch_bounds__(128) void k_agg1(const float* __restrict__ b1) {
    const int n = blockIdx.x;
    const int tid = threadIdx.x;
    __shared__ float4 red[128];
    __shared__ float s_ad[4];
    if (tid < 4) s_ad[tid] = g_adst1[n * HEADS + tid];
    __syncthreads();
    const int beg = g_row[n];
    const int end = g_row[n + 1];
    const float a0 = s_ad[0], a1 = s_ad[1], a2 = s_ad[2], a3 = s_ad[3];

    float4 mx = make_float4(-INFINITY, -INFINITY, -INFINITY, -INFINITY);
    for (int k = beg + tid; k < end; k += 128) {
        int s = g_csr[k];
        const float* as = &g_asrc1[s * HEADS];
        mx.x = fmaxf(mx.x, lrelu(as[0] + a0));
        mx.y = fmaxf(mx.y, lrelu(as[1] + a1));
        mx.z = fmaxf(mx.z, lrelu(as[2] + a2));
        mx.w = fmaxf(mx.w, lrelu(as[3] + a3));
    }
    red[tid] = mx;
    __syncthreads();
#pragma unroll
    for (int off = 64; off > 0; off >>= 1) {
        if (tid < off) {
            float4 u = red[tid], v = red[tid + off];
            u.x = fmaxf(u.x, v.x);
            u.y = fmaxf(u.y, v.y);
            u.z = fmaxf(u.z, v.z);
            u.w = fmaxf(u.w, v.w);
            red[tid] = u;
        }
        __syncthreads();
    }
    const float4 M4 = red[0];

    const int h = tid >> 5;
    const float mh = (h == 0) ? M4.x : (h == 1) ? M4.y : (h == 2) ? M4.z : M4.w;
    const float ah = (h == 0) ? a0 : (h == 1) ? a1 : (h == 2) ? a2 : a3;

    const float4* h1v = (const float4*)g_h1;
    float4 acc = make_float4(0.f, 0.f, 0.f, 0.f);
    float den = 0.f;
    for (int k = beg; k < end; k++) {
        int s = g_csr[k];
        float e = lrelu(g_asrc1[s * HEADS + h] + ah);
        float ex = expf(e - mh);
        den += ex;
        float4 hv = h1v[(size_t)s * 128 + tid];
        acc.x = fmaf(ex, hv.x, acc.x);
        acc.y = fmaf(ex, hv.y, acc.y);
        acc.z = fmaf(ex, hv.z, acc.z);
        acc.w = fmaf(ex, hv.w, acc.w);
    }
    const float inv = 1.f / (den + 1e-16f);
    float4 bb = ((const float4*)b1)[tid];
    float o0 = acc.x * inv + bb.x;
    float o1 = acc.y * inv + bb.y;
    float o2 = acc.z * inv + bb.z;
    float o3 = acc.w * inv + bb.w;
    o0 = o0 > 0.f ? o0 : expm1f(o0);
    o1 = o1 > 0.f ? o1 : expm1f(o1);
    o2 = o2 > 0.f ? o2 : expm1f(o2);
    o3 = o3 > 0.f ? o3 : expm1f(o3);
    ((float4*)g_act1)[(size_t)n * 128 + tid] = make_float4(o0, o1, o2, o3);
}

// ---------------- kernel: layer-2 GEMV (512->2) + attention scalars ----------------
__global__ __launch_bounds__(128) void k_l2(const float* __restrict__ W2,
                                            const float* __restrict__ as2,
                                            const float* __restrict__ ad2) {
    const int n = blockIdx.x;
    const int tid = threadIdx.x;
    __shared__ float2 red[128];
    float4 a = ((const float4*)g_act1)[(size_t)n * 128 + tid];
    float4 w01 = ((const float4*)W2)[tid * 2];
    float4 w23 = ((const float4*)W2)[tid * 2 + 1];
    float s0 = a.x * w01.x + a.y * w01.z + a.z * w23.x + a.w * w23.z;
    float s1 = a.x * w01.y + a.y * w01.w + a.z * w23.y + a.w * w23.w;
    red[tid] = make_float2(s0, s1);
    __syncthreads();
#pragma unroll
    for (int off = 64; off > 0; off >>= 1) {
        if (tid < off) {
            red[tid].x += red[tid + off].x;
            red[tid].y += red[tid + off].y;
        }
        __syncthreads();
    }
    if (tid == 0) {
        float h0 = red[0].x, h1 = red[0].y;
        g_h2[n * 2] = h0;
        g_h2[n * 2 + 1] = h1;
        g_asrc2[n] = h0 * as2[0] + h1 * as2[1];
        g_adst2[n] = h0 * ad2[0] + h1 * ad2[1];
    }
}

// ---------------- kernel: layer-2 aggregate (one warp per node) ----------------
__global__ __launch_bounds__(128) void k_agg2(const float* __restrict__ b2,
                                              float* __restrict__ out) {
    const int warp = threadIdx.x >> 5;
    const int lane = threadIdx.x & 31;
    const int n = blockIdx.x * 4 + warp;
    if (n >= N_NODES) return;
    const int beg = g_row[n];
    const int end = g_row[n + 1];
    const float ad = g_adst2[n];

    float mx = -INFINITY;
    for (int k = beg + lane; k < end; k += 32)
        mx = fmaxf(mx, lrelu(g_asrc2[g_csr[k]] + ad));
#pragma unroll
    for (int o = 16; o > 0; o >>= 1) mx = fmaxf(mx, __shfl_xor_sync(0xffffffffu, mx, o));

    float den = 0.f, c0 = 0.f, c1 = 0.f;
    for (int k = beg + lane; k < end; k += 32) {
        int s = g_csr[k];
        float e = lrelu(g_asrc2[s] + ad);
        float ex = expf(e - mx);
        den += ex;
        float2 hv = ((const float2*)g_h2)[s];
        c0 = fmaf(ex, hv.x, c0);
        c1 = fmaf(ex, hv.y, c1);
    }
#pragma unroll
    for (int o = 16; o > 0; o >>= 1) {
        den += __shfl_xor_sync(0xffffffffu, den, o);
        c0 += __shfl_xor_sync(0xffffffffu, c0, o);
        c1 += __shfl_xor_sync(0xffffffffu, c1, o);
    }
    if (lane == 0) {
        float inv = 1.f / (den + 1e-16f);
        out[n * 2] = c0 * inv + b2[0];
        out[n * 2 + 1] = c1 * inv + b2[1];
    }
}

// ---------------- launch (single stream) ----------------
extern "C" void kernel_launch(void* const* d_in, const int* in_sizes, int n_in,
                              void* d_out, int out_size) {
    const float* x   = (const float*)d_in[0];
    const int*   ei  = (const int*)d_in[1];
    const float* W1  = (const float*)d_in[2];
    const float* as1 = (const float*)d_in[3];
    const float* ad1 = (const float*)d_in[4];
    const float* b1  = (const float*)d_in[5];
    const float* W2  = (const float*)d_in[6];
    const float* as2 = (const float*)d_in[7];
    const float* ad2 = (const float*)d_in[8];
    const float* b2  = (const float*)d_in[9];
    float* out = (float*)d_out;

    k_zero<<<(N_NODES + 255) / 256, 256>>>();
    k_split_a<<<(N_NODES * 128 + 255) / 256, 256>>>(x);
    k_split_b<<<(IN_CH * D1 + 255) / 256, 256>>>(W1);
    k_gemm_mma<<<dim3((N_NODES + TBM - 1) / TBM, D1 / TBN), 256>>>();
    k_att1<<<N_NODES, 128>>>(as1, ad1);
    k_hist<<<(E2 + 255) / 256, 256>>>(ei);
    k_scan<<<1, 1024>>>();
    k_scatter<<<(E2 + 255) / 256, 256>>>(ei);
    k_agg1<<<N_NODES, 128>>>(b1);
    k_l2<<<N_NODES, 128>>>(W2, as2, ad2);
    k_agg2<<<(N_NODES + 3) / 4, 128>>>(b2, out);
}

// round 11
// speedup vs baseline: 1.3385x; 1.0566x over previous
#include <cuda_runtime.h>
#include <cuda_bf16.h>
#include <math.h>
#include <stdint.h>

#define N_NODES 10000
#define N_EDGES 320000
#define E2      (N_EDGES + N_NODES)   // + self loops
#define IN_CH   512
#define D1      512                   // HEADS * HID
#define HEADS   4
#define HID     128
#define NEG_SLOPE 0.2f
#define KBIG    1536                  // 3 * 512 (split-K trick)

// ---------------- scratch (no allocations allowed) ----------------
__device__ __align__(16) float g_h1  [N_NODES * D1];   // x @ W1 (fp32 result)
__device__ __align__(16) float g_act1[N_NODES * D1];   // elu(agg1 + b1)
__device__ float g_asrc1[N_NODES * HEADS];
__device__ float g_adst1[N_NODES * HEADS];
__device__ __align__(16) float g_h2[N_NODES * 2];
__device__ float g_asrc2[N_NODES];
__device__ float g_adst2[N_NODES];
__device__ int g_deg[N_NODES];
__device__ int g_row[N_NODES + 1];
__device__ int g_cur[N_NODES];
__device__ int g_csr[E2];
// split operands: A' = [ah | ah | al] (rows=M, K'=1536), B' = [bh | bl | bh] (rows=N=512)
__device__ __align__(16) unsigned short g_Abig[(size_t)N_NODES * KBIG];  // 30.7 MB bf16
__device__ __align__(16) unsigned short g_Bbig[(size_t)D1 * KBIG];      // 1.6 MB bf16

// ---------------- helpers ----------------
__device__ __forceinline__ float lrelu(float e) { return e > 0.f ? e : NEG_SLOPE * e; }

__device__ __forceinline__ unsigned short f2bf(float f) {
    __nv_bfloat16 b = __float2bfloat16(f);
    return *reinterpret_cast<unsigned short*>(&b);
}
__device__ __forceinline__ float bf2f(unsigned short u) {
    __nv_bfloat16 b;
    *reinterpret_cast<unsigned short*>(&b) = u;
    return __bfloat162float(b);
}
__device__ __forceinline__ uint32_t smem_u32(const void* p) {
    uint32_t a;
    asm("{ .reg .u64 t; cvta.to.shared.u64 t, %1; cvt.u32.u64 %0, t; }" : "=r"(a) : "l"(p));
    return a;
}

// ---------------- kernel: zero degree histogram ----------------
__global__ void k_zero() {
    int i = blockIdx.x * blockDim.x + threadIdx.x;
    if (i < N_NODES) g_deg[i] = 0;
}

// ---------------- split kernels: build A' and B' ----------------
__global__ __launch_bounds__(256) void k_split_a(const float* __restrict__ x) {
    int t = blockIdx.x * blockDim.x + threadIdx.x;  // N_NODES*128 threads, 4 elems each
    if (t >= N_NODES * 128) return;
    int m = t >> 7;
    int k4 = (t & 127) * 4;
    float4 v = *(const float4*)(x + (size_t)m * IN_CH + k4);
    unsigned short h0 = f2bf(v.x), h1 = f2bf(v.y), h2 = f2bf(v.z), h3 = f2bf(v.w);
    unsigned short l0 = f2bf(v.x - bf2f(h0)), l1 = f2bf(v.y - bf2f(h1));
    unsigned short l2 = f2bf(v.z - bf2f(h2)), l3 = f2bf(v.w - bf2f(h3));
    uint2 hi2 = make_uint2((uint32_t)h0 | ((uint32_t)h1 << 16),
                           (uint32_t)h2 | ((uint32_t)h3 << 16));
    uint2 lo2 = make_uint2((uint32_t)l0 | ((uint32_t)l1 << 16),
                           (uint32_t)l2 | ((uint32_t)l3 << 16));
    size_t base = (size_t)m * KBIG;
    *(uint2*)(g_Abig + base + k4) = hi2;          // ah
    *(uint2*)(g_Abig + base + 512 + k4) = hi2;    // ah
    *(uint2*)(g_Abig + base + 1024 + k4) = lo2;   // al
}

__global__ __launch_bounds__(256) void k_split_b(const float* __restrict__ W1) {
    int t = blockIdx.x * blockDim.x + threadIdx.x;  // 512*512
    if (t >= IN_CH * D1) return;
    int k = t >> 9;     // row of W1
    int n = t & 511;    // col of W1 -> row of B'
    float w = W1[(size_t)k * D1 + n];
    unsigned short h = f2bf(w);
    unsigned short l = f2bf(w - bf2f(h));
    size_t base = (size_t)n * KBIG;
    g_Bbig[base + k] = h;           // bh
    g_Bbig[base + 512 + k] = l;     // bl
    g_Bbig[base + 1024 + k] = h;    // bh
}

// ---------------- kernel: mma.sync bf16 GEMM  g_h1 = A' @ B'^T ----------------
// 128x128 CTA tile, 8 warps (2x4 -> 64x32 warp tile), BK=32, double-buffered.
// Fragment feeds via ldmatrix.x4 (conflict-free: 80B row stride = 20-bank step).
#define TBM 128
#define TBN 128
#define TBK 32
#define TNC (KBIG / TBK)     // 48 chunks
#define ASTR (TBK + 8)       // 40 shorts/row

__device__ __forceinline__ void mma16816(float* c, const uint32_t* a, const uint32_t* b) {
    asm volatile(
        "mma.sync.aligned.m16n8k16.row.col.f32.bf16.bf16.f32 "
        "{%0,%1,%2,%3}, {%4,%5,%6,%7}, {%8,%9}, {%0,%1,%2,%3};"
        : "+f"(c[0]), "+f"(c[1]), "+f"(c[2]), "+f"(c[3])
        : "r"(a[0]), "r"(a[1]), "r"(a[2]), "r"(a[3]), "r"(b[0]), "r"(b[1]));
}

__device__ __forceinline__ void ldsm4(uint32_t* r, uint32_t addr) {
    asm volatile("ldmatrix.sync.aligned.m8n8.x4.shared.b16 {%0,%1,%2,%3}, [%4];"
                 : "=r"(r[0]), "=r"(r[1]), "=r"(r[2]), "=r"(r[3])
                 : "r"(addr));
}

__global__ __launch_bounds__(256, 2) void k_gemm_mma() {
    __shared__ unsigned short As[2][TBM][ASTR];
    __shared__ unsigned short Bs[2][TBN][ASTR];
    const int tid = threadIdx.x;
    const int wid = tid >> 5;
    const int lane = tid & 31;
    const int g = lane >> 2;   // 0..7
    const int tg = lane & 3;   // 0..3
    const int wm = (wid & 1) * 64;
    const int wn = (wid >> 1) * 32;
    const int bm = blockIdx.x * TBM;
    const int bn = blockIdx.y * TBN;

    // ldmatrix per-lane source rows/cols (derived from the verified scalar mapping)
    // A matrix mi: row = wm + mi*16 + (lane&15), col = (lane>>4)*8  (+kb)
    const int a_r = wm + (lane & 15);
    const int a_c = (lane >> 4) << 3;
    // B matrix pair ni: row = wn + ni*8 + (lane&7) + ((lane&16)>>1), col = ((lane&8)?8:0) (+kb)
    const int b_r = wn + (lane & 7) + ((lane & 16) >> 1);
    const int b_c = (lane & 8);

    const uint32_t sA = smem_u32(&As[0][0][0]);
    const uint32_t sB = smem_u32(&Bs[0][0][0]);
    const uint32_t bufA = (uint32_t)(TBM * ASTR * 2);  // bytes per A buffer
    const uint32_t bufB = (uint32_t)(TBN * ASTR * 2);

    int garow[2], gbrow[2], lrow[2], lq[2];
#pragma unroll
    for (int i = 0; i < 2; i++) {
        int s = tid + i * 256;
        lrow[i] = s >> 2;
        lq[i] = (s & 3) * 8;  // short offset of 16B seg
        int gm = bm + lrow[i];
        garow[i] = (gm < N_NODES) ? gm : (N_NODES - 1);
        gbrow[i] = bn + lrow[i];  // < 512 always
    }

    float acc[4][4][4];
#pragma unroll
    for (int mi = 0; mi < 4; mi++)
#pragma unroll
        for (int ni = 0; ni < 4; ni++)
#pragma unroll
            for (int j = 0; j < 4; j++) acc[mi][ni][j] = 0.f;

    uint4 pa[2], pb[2];
#pragma unroll
    for (int i = 0; i < 2; i++) {
        pa[i] = *(const uint4*)(g_Abig + (size_t)garow[i] * KBIG + lq[i]);
        pb[i] = *(const uint4*)(g_Bbig + (size_t)gbrow[i] * KBIG + lq[i]);
    }
#pragma unroll
    for (int i = 0; i < 2; i++) {
        *(uint4*)&As[0][lrow[i]][lq[i]] = pa[i];
        *(uint4*)&Bs[0][lrow[i]][lq[i]] = pb[i];
    }
    __syncthreads();

    for (int c = 0; c < TNC; c++) {
        const int b = c & 1;
        if (c + 1 < TNC) {
            const int k0 = (c + 1) * TBK;
#pragma unroll
            for (int i = 0; i < 2; i++) {
                pa[i] = *(const uint4*)(g_Abig + (size_t)garow[i] * KBIG + k0 + lq[i]);
                pb[i] = *(const uint4*)(g_Bbig + (size_t)gbrow[i] * KBIG + k0 + lq[i]);
            }
        }
        const uint32_t aBase = sA + (uint32_t)b * bufA;
        const uint32_t bBase = sB + (uint32_t)b * bufB;
#pragma unroll
        for (int ks = 0; ks < 2; ks++) {
            const int kb = ks * 16;
            uint32_t af[4][4], bf[4][2];
#pragma unroll
            for (int mi = 0; mi < 4; mi++) {
                ldsm4(af[mi], aBase + (uint32_t)((a_r + mi * 16) * ASTR + kb + a_c) * 2);
            }
            {
                uint32_t t0[4], t1[4];
                ldsm4(t0, bBase + (uint32_t)((b_r) * ASTR + kb + b_c) * 2);        // ni 0,1
                ldsm4(t1, bBase + (uint32_t)((b_r + 16) * ASTR + kb + b_c) * 2);   // ni 2,3
                bf[0][0] = t0[0]; bf[0][1] = t0[1];
                bf[1][0] = t0[2]; bf[1][1] = t0[3];
                bf[2][0] = t1[0]; bf[2][1] = t1[1];
                bf[3][0] = t1[2]; bf[3][1] = t1[3];
            }
#pragma unroll
            for (int mi = 0; mi < 4; mi++)
#pragma unroll
                for (int ni = 0; ni < 4; ni++) mma16816(acc[mi][ni], af[mi], bf[ni]);
        }
        if (c + 1 < TNC) {
            const int nb = b ^ 1;
#pragma unroll
            for (int i = 0; i < 2; i++) {
                *(uint4*)&As[nb][lrow[i]][lq[i]] = pa[i];
                *(uint4*)&Bs[nb][lrow[i]][lq[i]] = pb[i];
            }
            __syncthreads();
        }
    }

    // epilogue: frag (mi,ni): c0,c1 -> (row, col..col+1), c2,c3 -> (row+8, ...)
#pragma unroll
    for (int mi = 0; mi < 4; mi++) {
        const int r0 = bm + wm + mi * 16 + g;
#pragma unroll
        for (int ni = 0; ni < 4; ni++) {
            const int col = bn + wn + ni * 8 + tg * 2;
            if (r0 < N_NODES)
                *(float2*)(g_h1 + (size_t)r0 * D1 + col) = make_float2(acc[mi][ni][0], acc[mi][ni][1]);
            if (r0 + 8 < N_NODES)
                *(float2*)(g_h1 + (size_t)(r0 + 8) * D1 + col) = make_float2(acc[mi][ni][2], acc[mi][ni][3]);
        }
    }
}

// ---------------- kernel: per-node attention scalars a_src1/a_dst1 ----------------
__global__ void k_att1(const float* __restrict__ as1, const float* __restrict__ ad1) {
    int n = blockIdx.x;
    int h = threadIdx.x >> 5;
    int lane = threadIdx.x & 31;
    float4 hv = ((const float4*)g_h1)[(size_t)n * 128 + h * 32 + lane];
    float4 sa = ((const float4*)as1)[h * 32 + lane];
    float4 da = ((const float4*)ad1)[h * 32 + lane];
    float s = hv.x * sa.x + hv.y * sa.y + hv.z * sa.z + hv.w * sa.w;
    float d = hv.x * da.x + hv.y * da.y + hv.z * da.z + hv.w * da.w;
#pragma unroll
    for (int o = 16; o > 0; o >>= 1) {
        s += __shfl_xor_sync(0xffffffffu, s, o);
        d += __shfl_xor_sync(0xffffffffu, d, o);
    }
    if (lane == 0) {
        g_asrc1[n * HEADS + h] = s;
        g_adst1[n * HEADS + h] = d;
    }
}

// ---------------- CSR build: histogram / scan / scatter ----------------
__global__ void k_hist(const int* __restrict__ ei) {
    int e = blockIdx.x * blockDim.x + threadIdx.x;
    if (e >= E2) return;
    int dst = (e < N_EDGES) ? ei[N_EDGES + e] : (e - N_EDGES);
    atomicAdd(&g_deg[dst], 1);
}

__global__ void k_scan() {
    __shared__ int part[1024];
    const int tid = threadIdx.x;
    const int CH = (N_NODES + 1023) / 1024;  // 10
    int base = tid * CH;
    int s = 0;
    for (int i = 0; i < CH; i++) {
        int idx = base + i;
        if (idx < N_NODES) s += g_deg[idx];
    }
    part[tid] = s;
    __syncthreads();
    for (int off = 1; off < 1024; off <<= 1) {
        int v = (tid >= off) ? part[tid - off] : 0;
        __syncthreads();
        part[tid] += v;
        __syncthreads();
    }
    int run = (tid == 0) ? 0 : part[tid - 1];
    for (int i = 0; i < CH; i++) {
        int idx = base + i;
        if (idx < N_NODES) {
            g_row[idx] = run;
            g_cur[idx] = run;
            run += g_deg[idx];
        }
    }
    if (tid == 1023) g_row[N_NODES] = part[1023];
}

__global__ void k_scatter(const int* __restrict__ ei) {
    int e = blockIdx.x * blockDim.x + threadIdx.x;
    if (e >= E2) return;
    int src, dst;
    if (e < N_EDGES) {
        src = ei[e];
        dst = ei[N_EDGES + e];
    } else {
        src = dst = e - N_EDGES;
    }
    int p = atomicAdd(&g_cur[dst], 1);
    g_csr[p] = src;
}

// ---------------- kernel: layer-1 softmax-aggregate + bias + ELU ----------------
__global__ __launch_bounds__(128) void k_agg1(const float* __restrict__ b1) {
    const int n = blockIdx.x;
    const int tid = threadIdx.x;
    __shared__ float4 red[128];
    __shared__ float s_ad[4];
    if (tid < 4) s_ad[tid] = g_adst1[n * HEADS + tid];
    __syncthreads();
    const int beg = g_row[n];
    const int end = g_row[n + 1];
    const float a0 = s_ad[0], a1 = s_ad[1], a2 = s_ad[2], a3 = s_ad[3];

    float4 mx = make_float4(-INFINITY, -INFINITY, -INFINITY, -INFINITY);
    for (int k = beg + tid; k < end; k += 128) {
        int s = g_csr[k];
        const float* as = &g_asrc1[s * HEADS];
        mx.x = fmaxf(mx.x, lrelu(as[0] + a0));
        mx.y = fmaxf(mx.y, lrelu(as[1] + a1));
        mx.z = fmaxf(mx.z, lrelu(as[2] + a2));
        mx.w = fmaxf(mx.w, lrelu(as[3] + a3));
    }
    red[tid] = mx;
    __syncthreads();
#pragma unroll
    for (int off = 64; off > 0; off >>= 1) {
        if (tid < off) {
            float4 u = red[tid], v = red[tid + off];
            u.x = fmaxf(u.x, v.x);
            u.y = fmaxf(u.y, v.y);
            u.z = fmaxf(u.z, v.z);
            u.w = fmaxf(u.w, v.w);
            red[tid] = u;
        }
        __syncthreads();
    }
    const float4 M4 = red[0];

    const int h = tid >> 5;
    const float mh = (h == 0) ? M4.x : (h == 1) ? M4.y : (h == 2) ? M4.z : M4.w;
    const float ah = (h == 0) ? a0 : (h == 1) ? a1 : (h == 2) ? a2 : a3;

    const float4* h1v = (const float4*)g_h1;
    float4 acc = make_float4(0.f, 0.f, 0.f, 0.f);
    float den = 0.f;
    for (int k = beg; k < end; k++) {
        int s = g_csr[k];
        float e = lrelu(g_asrc1[s * HEADS + h] + ah);
        float ex = expf(e - mh);
        den += ex;
        float4 hv = h1v[(size_t)s * 128 + tid];
        acc.x = fmaf(ex, hv.x, acc.x);
        acc.y = fmaf(ex, hv.y, acc.y);
        acc.z = fmaf(ex, hv.z, acc.z);
        acc.w = fmaf(ex, hv.w, acc.w);
    }
    const float inv = 1.f / (den + 1e-16f);
    float4 bb = ((const float4*)b1)[tid];
    float o0 = acc.x * inv + bb.x;
    float o1 = acc.y * inv + bb.y;
    float o2 = acc.z * inv + bb.z;
    float o3 = acc.w * inv + bb.w;
    o0 = o0 > 0.f ? o0 : expm1f(o0);
    o1 = o1 > 0.f ? o1 : expm1f(o1);
    o2 = o2 > 0.f ? o2 : expm1f(o2);
    o3 = o3 > 0.f ? o3 : expm1f(o3);
    ((float4*)g_act1)[(size_t)n * 128 + tid] = make_float4(o0, o1, o2, o3);
}

// ---------------- kernel: layer-2 GEMV (512->2) + attention scalars ----------------
__global__ __launch_bounds__(128) void k_l2(const float* __restrict__ W2,
                                            const float* __restrict__ as2,
                                            const float* __restrict__ ad2) {
    const int n = blockIdx.x;
    const int tid = threadIdx.x;
    __shared__ float2 red[128];
    float4 a = ((const float4*)g_act1)[(size_t)n * 128 + tid];
    float4 w01 = ((const float4*)W2)[tid * 2];
    float4 w23 = ((const float4*)W2)[tid * 2 + 1];
    float s0 = a.x * w01.x + a.y * w01.z + a.z * w23.x + a.w * w23.z;
    float s1 = a.x * w01.y + a.y * w01.w + a.z * w23.y + a.w * w23.w;
    red[tid] = make_float2(s0, s1);
    __syncthreads();
#pragma unroll
    for (int off = 64; off > 0; off >>= 1) {
        if (tid < off) {
            red[tid].x += red[tid + off].x;
            red[tid].y += red[tid + off].y;
        }
        __syncthreads();
    }
    if (tid == 0) {
        float h0 = red[0].x, h1 = red[0].y;
        g_h2[n * 2] = h0;
        g_h2[n * 2 + 1] = h1;
        g_asrc2[n] = h0 * as2[0] + h1 * as2[1];
        g_adst2[n] = h0 * ad2[0] + h1 * ad2[1];
    }
}

// ---------------- kernel: layer-2 aggregate (one warp per node) ----------------
__global__ __launch_bounds__(128) void k_agg2(const float* __restrict__ b2,
                                              float* __restrict__ out) {
    const int warp = threadIdx.x >> 5;
    const int lane = threadIdx.x & 31;
    const int n = blockIdx.x * 4 + warp;
    if (n >= N_NODES) return;
    const int beg = g_row[n];
    const int end = g_row[n + 1];
    const float ad = g_adst2[n];

    float mx = -INFINITY;
    for (int k = beg + lane; k < end; k += 32)
        mx = fmaxf(mx, lrelu(g_asrc2[g_csr[k]] + ad));
#pragma unroll
    for (int o = 16; o > 0; o >>= 1) mx = fmaxf(mx, __shfl_xor_sync(0xffffffffu, mx, o));

    float den = 0.f, c0 = 0.f, c1 = 0.f;
    for (int k = beg + lane; k < end; k += 32) {
        int s = g_csr[k];
        float e = lrelu(g_asrc2[s] + ad);
        float ex = expf(e - mx);
        den += ex;
        float2 hv = ((const float2*)g_h2)[s];
        c0 = fmaf(ex, hv.x, c0);
        c1 = fmaf(ex, hv.y, c1);
    }
#pragma unroll
    for (int o = 16; o > 0; o >>= 1) {
        den += __shfl_xor_sync(0xffffffffu, den, o);
        c0 += __shfl_xor_sync(0xffffffffu, c0, o);
        c1 += __shfl_xor_sync(0xffffffffu, c1, o);
    }
    if (lane == 0) {
        float inv = 1.f / (den + 1e-16f);
        out[n * 2] = c0 * inv + b2[0];
        out[n * 2 + 1] = c1 * inv + b2[1];
    }
}

// ---------------- launch (single stream) ----------------
extern "C" void kernel_launch(void* const* d_in, const int* in_sizes, int n_in,
                              void* d_out, int out_size) {
    const float* x   = (const float*)d_in[0];
    const int*   ei  = (const int*)d_in[1];
    const float* W1  = (const float*)d_in[2];
    const float* as1 = (const float*)d_in[3];
    const float* ad1 = (const float*)d_in[4];
    const float* b1  = (const float*)d_in[5];
    const float* W2  = (const float*)d_in[6];
    const float* as2 = (const float*)d_in[7];
    const float* ad2 = (const float*)d_in[8];
    const float* b2  = (const float*)d_in[9];
    float* out = (float*)d_out;

    k_zero<<<(N_NODES + 255) / 256, 256>>>();
    k_split_a<<<(N_NODES * 128 + 255) / 256, 256>>>(x);
    k_split_b<<<(IN_CH * D1 + 255) / 256, 256>>>(W1);
    k_gemm_mma<<<dim3((N_NODES + TBM - 1) / TBM, D1 / TBN), 256>>>();
    k_att1<<<N_NODES, 128>>>(as1, ad1);
    k_hist<<<(E2 + 255) / 256, 256>>>(ei);
    k_scan<<<1, 1024>>>();
    k_scatter<<<(E2 + 255) / 256, 256>>>(ei);
    k_agg1<<<N_NODES, 128>>>(b1);
    k_l2<<<N_NODES, 128>>>(W2, as2, ad2);
    k_agg2<<<(N_NODES + 3) / 4, 128>>>(b2, out);
}

// round 12
// speedup vs baseline: 1.3848x; 1.0346x over previous
#include <cuda_runtime.h>
#include <cuda_bf16.h>
#include <math.h>
#include <stdint.h>

#define N_NODES 10000
#define N_EDGES 320000
#define E2      (N_EDGES + N_NODES)   // + self loops
#define IN_CH   512
#define D1      512                   // HEADS * HID
#define HEADS   4
#define HID     128
#define NEG_SLOPE 0.2f
#define KBIG    1536                  // 3 * 512 (split-K trick)

// ---------------- scratch (no allocations allowed) ----------------
__device__ __align__(16) float g_h1  [N_NODES * D1];   // x @ W1 (fp32 result)
__device__ __align__(16) float g_act1[N_NODES * D1];   // elu(agg1 + b1)
__device__ float g_asrc1[N_NODES * HEADS];
__device__ float g_adst1[N_NODES * HEADS];
__device__ __align__(16) float g_h2[N_NODES * 2];
__device__ float g_asrc2[N_NODES];
__device__ float g_adst2[N_NODES];
__device__ int g_deg[N_NODES];
__device__ int g_row[N_NODES + 1];
__device__ int g_cur[N_NODES];
__device__ int g_csr[E2];
// split operands: A' = [ah | ah | al] (rows=M, K'=1536), B' = [bh | bl | bh] (rows=N=512)
__device__ __align__(16) unsigned short g_Abig[(size_t)N_NODES * KBIG];  // 30.7 MB bf16
__device__ __align__(16) unsigned short g_Bbig[(size_t)D1 * KBIG];      // 1.6 MB bf16

// ---------------- helpers ----------------
__device__ __forceinline__ float lrelu(float e) { return e > 0.f ? e : NEG_SLOPE * e; }

__device__ __forceinline__ unsigned short f2bf(float f) {
    __nv_bfloat16 b = __float2bfloat16(f);
    return *reinterpret_cast<unsigned short*>(&b);
}
__device__ __forceinline__ float bf2f(unsigned short u) {
    __nv_bfloat16 b;
    *reinterpret_cast<unsigned short*>(&b) = u;
    return __bfloat162float(b);
}
__device__ __forceinline__ uint32_t smem_u32(const void* p) {
    uint32_t a;
    asm("{ .reg .u64 t; cvta.to.shared.u64 t, %1; cvt.u32.u64 %0, t; }" : "=r"(a) : "l"(p));
    return a;
}

// ---------------- kernel: zero degree histogram ----------------
__global__ void k_zero() {
    int i = blockIdx.x * blockDim.x + threadIdx.x;
    if (i < N_NODES) g_deg[i] = 0;
}

// ---------------- split kernels: build A' and B' ----------------
__global__ __launch_bounds__(256) void k_split_a(const float* __restrict__ x) {
    int t = blockIdx.x * blockDim.x + threadIdx.x;  // N_NODES*128 threads, 4 elems each
    if (t >= N_NODES * 128) return;
    int m = t >> 7;
    int k4 = (t & 127) * 4;
    float4 v = *(const float4*)(x + (size_t)m * IN_CH + k4);
    unsigned short h0 = f2bf(v.x), h1 = f2bf(v.y), h2 = f2bf(v.z), h3 = f2bf(v.w);
    unsigned short l0 = f2bf(v.x - bf2f(h0)), l1 = f2bf(v.y - bf2f(h1));
    unsigned short l2 = f2bf(v.z - bf2f(h2)), l3 = f2bf(v.w - bf2f(h3));
    uint2 hi2 = make_uint2((uint32_t)h0 | ((uint32_t)h1 << 16),
                           (uint32_t)h2 | ((uint32_t)h3 << 16));
    uint2 lo2 = make_uint2((uint32_t)l0 | ((uint32_t)l1 << 16),
                           (uint32_t)l2 | ((uint32_t)l3 << 16));
    size_t base = (size_t)m * KBIG;
    *(uint2*)(g_Abig + base + k4) = hi2;          // ah
    *(uint2*)(g_Abig + base + 512 + k4) = hi2;    // ah
    *(uint2*)(g_Abig + base + 1024 + k4) = lo2;   // al
}

__global__ __launch_bounds__(256) void k_split_b(const float* __restrict__ W1) {
    int t = blockIdx.x * blockDim.x + threadIdx.x;  // 512*512
    if (t >= IN_CH * D1) return;
    int k = t >> 9;     // row of W1
    int n = t & 511;    // col of W1 -> row of B'
    float w = W1[(size_t)k * D1 + n];
    unsigned short h = f2bf(w);
    unsigned short l = f2bf(w - bf2f(h));
    size_t base = (size_t)n * KBIG;
    g_Bbig[base + k] = h;           // bh
    g_Bbig[base + 512 + k] = l;     // bl
    g_Bbig[base + 1024 + k] = h;    // bh
}

// ---------------- kernel: mma.sync bf16 GEMM  g_h1 = A' @ B'^T ----------------
// 128x128 CTA tile, 8 warps (2x4 -> 64x32 warp tile), BK=32.
// 4-stage cp.async pipeline (gmem->smem, no register staging); ldmatrix feeds.
#define TBM 128
#define TBN 128
#define TBK 32
#define TNC (KBIG / TBK)     // 48 chunks
#define ASTR (TBK + 8)       // 40 shorts/row (80B stride: conflict-free ldmatrix)
#define NSTAGE 4
#define SSZ ((TBM + TBN) * ASTR * 2)   // 20480 B per stage
#define BOFF (TBM * ASTR * 2)          // 10240 B: B tile offset within stage
#define GSMEM (NSTAGE * SSZ)           // 81920 B

__device__ __forceinline__ void mma16816(float* c, const uint32_t* a, const uint32_t* b) {
    asm volatile(
        "mma.sync.aligned.m16n8k16.row.col.f32.bf16.bf16.f32 "
        "{%0,%1,%2,%3}, {%4,%5,%6,%7}, {%8,%9}, {%0,%1,%2,%3};"
        : "+f"(c[0]), "+f"(c[1]), "+f"(c[2]), "+f"(c[3])
        : "r"(a[0]), "r"(a[1]), "r"(a[2]), "r"(a[3]), "r"(b[0]), "r"(b[1]));
}
__device__ __forceinline__ void ldsm4(uint32_t* r, uint32_t addr) {
    asm volatile("ldmatrix.sync.aligned.m8n8.x4.shared.b16 {%0,%1,%2,%3}, [%4];"
                 : "=r"(r[0]), "=r"(r[1]), "=r"(r[2]), "=r"(r[3])
                 : "r"(addr));
}
__device__ __forceinline__ void cpasync16(uint32_t dst, const void* src) {
    asm volatile("cp.async.cg.shared.global [%0], [%1], 16;" :: "r"(dst), "l"(src));
}
__device__ __forceinline__ void cp_commit() {
    asm volatile("cp.async.commit_group;" ::: "memory");
}
template <int N>
__device__ __forceinline__ void cp_wait() {
    asm volatile("cp.async.wait_group %0;" :: "n"(N) : "memory");
}

__global__ __launch_bounds__(256, 2) void k_gemm_mma() {
    extern __shared__ unsigned short smbuf[];
    const uint32_t sbase = smem_u32(smbuf);
    const int tid = threadIdx.x;
    const int wid = tid >> 5;
    const int lane = tid & 31;
    const int g = lane >> 2;   // 0..7
    const int tg = lane & 3;   // 0..3
    const int wm = (wid & 1) * 64;
    const int wn = (wid >> 1) * 32;
    const int bm = blockIdx.x * TBM;
    const int bn = blockIdx.y * TBN;

    // ldmatrix per-lane source rows/cols
    const int a_r = wm + (lane & 15);
    const int a_c = (lane >> 4) << 3;
    const int b_r = wn + (lane & 7) + ((lane & 16) >> 1);
    const int b_c = (lane & 8);

    // loader mapping: per tile 128 rows x 64B = 512 x 16B segs; 2 A + 2 B per thread
    int lrow[2], lq[2], garow[2], gbrow[2];
#pragma unroll
    for (int i = 0; i < 2; i++) {
        int s = tid + i * 256;
        lrow[i] = s >> 2;
        lq[i] = (s & 3) * 8;  // short offset of 16B seg
        int gm = bm + lrow[i];
        garow[i] = (gm < N_NODES) ? gm : (N_NODES - 1);
        gbrow[i] = bn + lrow[i];  // < 512 always
    }

    float acc[4][4][4];
#pragma unroll
    for (int mi = 0; mi < 4; mi++)
#pragma unroll
        for (int ni = 0; ni < 4; ni++)
#pragma unroll
            for (int j = 0; j < 4; j++) acc[mi][ni][j] = 0.f;

    // async load of chunk c into stage c&3
#define ISSUE(c)                                                                       \
    do {                                                                               \
        const uint32_t st_ = sbase + (uint32_t)((c) & 3) * SSZ;                        \
        const int k0_ = (c) * TBK;                                                     \
        _Pragma("unroll") for (int i = 0; i < 2; i++) {                                \
            cpasync16(st_ + (uint32_t)(lrow[i] * ASTR + lq[i]) * 2,                    \
                      g_Abig + (size_t)garow[i] * KBIG + k0_ + lq[i]);                 \
            cpasync16(st_ + BOFF + (uint32_t)(lrow[i] * ASTR + lq[i]) * 2,             \
                      g_Bbig + (size_t)gbrow[i] * KBIG + k0_ + lq[i]);                 \
        }                                                                              \
        cp_commit();                                                                   \
    } while (0)

    ISSUE(0);
    ISSUE(1);
    ISSUE(2);

    for (int c = 0; c < TNC; c++) {
        cp_wait<2>();      // chunk c resident
        __syncthreads();   // all warps done with stage (c-1)&3 and see chunk c
        if (c + 3 < TNC) ISSUE(c + 3);  // fills stage (c-1)&3, freed by barrier above
        const uint32_t aB = sbase + (uint32_t)(c & 3) * SSZ;
        const uint32_t bB = aB + BOFF;
#pragma unroll
        for (int ks = 0; ks < 2; ks++) {
            const int kb = ks * 16;
            uint32_t af[4][4], bf[4][2];
#pragma unroll
            for (int mi = 0; mi < 4; mi++) {
                ldsm4(af[mi], aB + (uint32_t)((a_r + mi * 16) * ASTR + kb + a_c) * 2);
            }
            {
                uint32_t t0[4], t1[4];
                ldsm4(t0, bB + (uint32_t)((b_r) * ASTR + kb + b_c) * 2);       // ni 0,1
                ldsm4(t1, bB + (uint32_t)((b_r + 16) * ASTR + kb + b_c) * 2);  // ni 2,3
                bf[0][0] = t0[0]; bf[0][1] = t0[1];
                bf[1][0] = t0[2]; bf[1][1] = t0[3];
                bf[2][0] = t1[0]; bf[2][1] = t1[1];
                bf[3][0] = t1[2]; bf[3][1] = t1[3];
            }
#pragma unroll
            for (int mi = 0; mi < 4; mi++)
#pragma unroll
                for (int ni = 0; ni < 4; ni++) mma16816(acc[mi][ni], af[mi], bf[ni]);
        }
    }
#undef ISSUE

    // epilogue: frag (mi,ni): c0,c1 -> (row, col..col+1), c2,c3 -> (row+8, ...)
#pragma unroll
    for (int mi = 0; mi < 4; mi++) {
        const int r0 = bm + wm + mi * 16 + g;
#pragma unroll
        for (int ni = 0; ni < 4; ni++) {
            const int col = bn + wn + ni * 8 + tg * 2;
            if (r0 < N_NODES)
                *(float2*)(g_h1 + (size_t)r0 * D1 + col) = make_float2(acc[mi][ni][0], acc[mi][ni][1]);
            if (r0 + 8 < N_NODES)
                *(float2*)(g_h1 + (size_t)(r0 + 8) * D1 + col) = make_float2(acc[mi][ni][2], acc[mi][ni][3]);
        }
    }
}

// ---------------- kernel: per-node attention scalars a_src1/a_dst1 ----------------
__global__ void k_att1(const float* __restrict__ as1, const float* __restrict__ ad1) {
    int n = blockIdx.x;
    int h = threadIdx.x >> 5;
    int lane = threadIdx.x & 31;
    float4 hv = ((const float4*)g_h1)[(size_t)n * 128 + h * 32 + lane];
    float4 sa = ((const float4*)as1)[h * 32 + lane];
    float4 da = ((const float4*)ad1)[h * 32 + lane];
    float s = hv.x * sa.x + hv.y * sa.y + hv.z * sa.z + hv.w * sa.w;
    float d = hv.x * da.x + hv.y * da.y + hv.z * da.z + hv.w * da.w;
#pragma unroll
    for (int o = 16; o > 0; o >>= 1) {
        s += __shfl_xor_sync(0xffffffffu, s, o);
        d += __shfl_xor_sync(0xffffffffu, d, o);
    }
    if (lane == 0) {
        g_asrc1[n * HEADS + h] = s;
        g_adst1[n * HEADS + h] = d;
    }
}

// ---------------- CSR build: histogram / scan / scatter ----------------
__global__ void k_hist(const int* __restrict__ ei) {
    int e = blockIdx.x * blockDim.x + threadIdx.x;
    if (e >= E2) return;
    int dst = (e < N_EDGES) ? ei[N_EDGES + e] : (e - N_EDGES);
    atomicAdd(&g_deg[dst], 1);
}

__global__ void k_scan() {
    __shared__ int part[1024];
    const int tid = threadIdx.x;
    const int CH = (N_NODES + 1023) / 1024;  // 10
    int base = tid * CH;
    int s = 0;
    for (int i = 0; i < CH; i++) {
        int idx = base + i;
        if (idx < N_NODES) s += g_deg[idx];
    }
    part[tid] = s;
    __syncthreads();
    for (int off = 1; off < 1024; off <<= 1) {
        int v = (tid >= off) ? part[tid - off] : 0;
        __syncthreads();
        part[tid] += v;
        __syncthreads();
    }
    int run = (tid == 0) ? 0 : part[tid - 1];
    for (int i = 0; i < CH; i++) {
        int idx = base + i;
        if (idx < N_NODES) {
            g_row[idx] = run;
            g_cur[idx] = run;
            run += g_deg[idx];
        }
    }
    if (tid == 1023) g_row[N_NODES] = part[1023];
}

__global__ void k_scatter(const int* __restrict__ ei) {
    int e = blockIdx.x * blockDim.x + threadIdx.x;
    if (e >= E2) return;
    int src, dst;
    if (e < N_EDGES) {
        src = ei[e];
        dst = ei[N_EDGES + e];
    } else {
        src = dst = e - N_EDGES;
    }
    int p = atomicAdd(&g_cur[dst], 1);
    g_csr[p] = src;
}

// ---------------- kernel: layer-1 softmax-aggregate + bias + ELU ----------------
__global__ __launch_bounds__(128) void k_agg1(const float* __restrict__ b1) {
    const int n = blockIdx.x;
    const int tid = threadIdx.x;
    __shared__ float4 red[128];
    __shared__ float s_ad[4];
    if (tid < 4) s_ad[tid] = g_adst1[n * HEADS + tid];
    __syncthreads();
    const int beg = g_row[n];
    const int end = g_row[n + 1];
    const float a0 = s_ad[0], a1 = s_ad[1], a2 = s_ad[2], a3 = s_ad[3];

    float4 mx = make_float4(-INFINITY, -INFINITY, -INFINITY, -INFINITY);
    for (int k = beg + tid; k < end; k += 128) {
        int s = g_csr[k];
        const float* as = &g_asrc1[s * HEADS];
        mx.x = fmaxf(mx.x, lrelu(as[0] + a0));
        mx.y = fmaxf(mx.y, lrelu(as[1] + a1));
        mx.z = fmaxf(mx.z, lrelu(as[2] + a2));
        mx.w = fmaxf(mx.w, lrelu(as[3] + a3));
    }
    red[tid] = mx;
    __syncthreads();
#pragma unroll
    for (int off = 64; off > 0; off >>= 1) {
        if (tid < off) {
            float4 u = red[tid], v = red[tid + off];
            u.x = fmaxf(u.x, v.x);
            u.y = fmaxf(u.y, v.y);
            u.z = fmaxf(u.z, v.z);
            u.w = fmaxf(u.w, v.w);
            red[tid] = u;
        }
        __syncthreads();
    }
    const float4 M4 = red[0];

    const int h = tid >> 5;
    const float mh = (h == 0) ? M4.x : (h == 1) ? M4.y : (h == 2) ? M4.z : M4.w;
    const float ah = (h == 0) ? a0 : (h == 1) ? a1 : (h == 2) ? a2 : a3;

    const float4* h1v = (const float4*)g_h1;
    float4 acc = make_float4(0.f, 0.f, 0.f, 0.f);
    float den = 0.f;
    for (int k = beg; k < end; k++) {
        int s = g_csr[k];
        float e = lrelu(g_asrc1[s * HEADS + h] + ah);
        float ex = expf(e - mh);
        den += ex;
        float4 hv = h1v[(size_t)s * 128 + tid];
        acc.x = fmaf(ex, hv.x, acc.x);
        acc.y = fmaf(ex, hv.y, acc.y);
        acc.z = fmaf(ex, hv.z, acc.z);
        acc.w = fmaf(ex, hv.w, acc.w);
    }
    const float inv = 1.f / (den + 1e-16f);
    float4 bb = ((const float4*)b1)[tid];
    float o0 = acc.x * inv + bb.x;
    float o1 = acc.y * inv + bb.y;
    float o2 = acc.z * inv + bb.z;
    float o3 = acc.w * inv + bb.w;
    o0 = o0 > 0.f ? o0 : expm1f(o0);
    o1 = o1 > 0.f ? o1 : expm1f(o1);
    o2 = o2 > 0.f ? o2 : expm1f(o2);
    o3 = o3 > 0.f ? o3 : expm1f(o3);
    ((float4*)g_act1)[(size_t)n * 128 + tid] = make_float4(o0, o1, o2, o3);
}

// ---------------- kernel: layer-2 GEMV (512->2) + attention scalars ----------------
__global__ __launch_bounds__(128) void k_l2(const float* __restrict__ W2,
                                            const float* __restrict__ as2,
                                            const float* __restrict__ ad2) {
    const int n = blockIdx.x;
    const int tid = threadIdx.x;
    __shared__ float2 red[128];
    float4 a = ((const float4*)g_act1)[(size_t)n * 128 + tid];
    float4 w01 = ((const float4*)W2)[tid * 2];
    float4 w23 = ((const float4*)W2)[tid * 2 + 1];
    float s0 = a.x * w01.x + a.y * w01.z + a.z * w23.x + a.w * w23.z;
    float s1 = a.x * w01.y + a.y * w01.w + a.z * w23.y + a.w * w23.w;
    red[tid] = make_float2(s0, s1);
    __syncthreads();
#pragma unroll
    for (int off = 64; off > 0; off >>= 1) {
        if (tid < off) {
            red[tid].x += red[tid + off].x;
            red[tid].y += red[tid + off].y;
        }
        __syncthreads();
    }
    if (tid == 0) {
        float h0 = red[0].x, h1 = red[0].y;
        g_h2[n * 2] = h0;
        g_h2[n * 2 + 1] = h1;
        g_asrc2[n] = h0 * as2[0] + h1 * as2[1];
        g_adst2[n] = h0 * ad2[0] + h1 * ad2[1];
    }
}

// ---------------- kernel: layer-2 aggregate (one warp per node) ----------------
__global__ __launch_bounds__(128) void k_agg2(const float* __restrict__ b2,
                                              float* __restrict__ out) {
    const int warp = threadIdx.x >> 5;
    const int lane = threadIdx.x & 31;
    const int n = blockIdx.x * 4 + warp;
    if (n >= N_NODES) return;
    const int beg = g_row[n];
    const int end = g_row[n + 1];
    const float ad = g_adst2[n];

    float mx = -INFINITY;
    for (int k = beg + lane; k < end; k += 32)
        mx = fmaxf(mx, lrelu(g_asrc2[g_csr[k]] + ad));
#pragma unroll
    for (int o = 16; o > 0; o >>= 1) mx = fmaxf(mx, __shfl_xor_sync(0xffffffffu, mx, o));

    float den = 0.f, c0 = 0.f, c1 = 0.f;
    for (int k = beg + lane; k < end; k += 32) {
        int s = g_csr[k];
        float e = lrelu(g_asrc2[s] + ad);
        float ex = expf(e - mx);
        den += ex;
        float2 hv = ((const float2*)g_h2)[s];
        c0 = fmaf(ex, hv.x, c0);
        c1 = fmaf(ex, hv.y, c1);
    }
#pragma unroll
    for (int o = 16; o > 0; o >>= 1) {
        den += __shfl_xor_sync(0xffffffffu, den, o);
        c0 += __shfl_xor_sync(0xffffffffu, c0, o);
        c1 += __shfl_xor_sync(0xffffffffu, c1, o);
    }
    if (lane == 0) {
        float inv = 1.f / (den + 1e-16f);
        out[n * 2] = c0 * inv + b2[0];
        out[n * 2 + 1] = c1 * inv + b2[1];
    }
}

// ---------------- launch (single stream) ----------------
extern "C" void kernel_launch(void* const* d_in, const int* in_sizes, int n_in,
                              void* d_out, int out_size) {
    const float* x   = (const float*)d_in[0];
    const int*   ei  = (const int*)d_in[1];
    const float* W1  = (const float*)d_in[2];
    const float* as1 = (const float*)d_in[3];
    const float* ad1 = (const float*)d_in[4];
    const float* b1  = (const float*)d_in[5];
    const float* W2  = (const float*)d_in[6];
    const float* as2 = (const float*)d_in[7];
    const float* ad2 = (const float*)d_in[8];
    const float* b2  = (const float*)d_in[9];
    float* out = (float*)d_out;

    cudaFuncSetAttribute(k_gemm_mma, cudaFuncAttributeMaxDynamicSharedMemorySize, GSMEM);

    k_zero<<<(N_NODES + 255) / 256, 256>>>();
    k_split_a<<<(N_NODES * 128 + 255) / 256, 256>>>(x);
    k_split_b<<<(IN_CH * D1 + 255) / 256, 256>>>(W1);
    k_gemm_mma<<<dim3((N_NODES + TBM - 1) / TBM, D1 / TBN), 256, GSMEM>>>();
    k_att1<<<N_NODES, 128>>>(as1, ad1);
    k_hist<<<(E2 + 255) / 256, 256>>>(ei);
    k_scan<<<1, 1024>>>();
    k_scatter<<<(E2 + 255) / 256, 256>>>(ei);
    k_agg1<<<N_NODES, 128>>>(b1);
    k_l2<<<N_NODES, 128>>>(W2, as2, ad2);
    k_agg2<<<(N_NODES + 3) / 4, 128>>>(b2, out);
}

// round 16
// speedup vs baseline: 1.4750x; 1.0651x over previous
#include <cuda_runtime.h>
#include <cuda_bf16.h>
#include <math.h>
#include <stdint.h>

#define N_NODES 10000
#define N_EDGES 320000
#define E2      (N_EDGES + N_NODES)   // + self loops
#define IN_CH   512
#define D1      512                   // HEADS * HID
#define HEADS   4
#define HID     128
#define NEG_SLOPE 0.2f
#define KBIG    1536                  // 3 * 512 (split-K trick)

// ---------------- scratch (no allocations allowed) ----------------
__device__ __align__(16) float g_h1  [N_NODES * D1];   // x @ W1 (fp32 result)
__device__ __align__(16) float g_act1[N_NODES * D1];   // elu(agg1 + b1)
__device__ float g_asrc1[N_NODES * HEADS];
__device__ float g_adst1[N_NODES * HEADS];
__device__ __align__(16) float g_h2[N_NODES * 2];
__device__ float g_asrc2[N_NODES];
__device__ float g_adst2[N_NODES];
__device__ int g_deg[N_NODES];
__device__ int g_row[N_NODES + 1];
__device__ int g_cur[N_NODES];
__device__ int g_csr[E2];
// split operands: A' = [ah | ah | al] (rows=M, K'=1536), B' = [bh | bl | bh] (rows=N=512)
__device__ __align__(16) unsigned short g_Abig[(size_t)N_NODES * KBIG];  // 30.7 MB bf16
__device__ __align__(16) unsigned short g_Bbig[(size_t)D1 * KBIG];      // 1.6 MB bf16

// ---------------- helpers ----------------
__device__ __forceinline__ float lrelu(float e) { return e > 0.f ? e : NEG_SLOPE * e; }

__device__ __forceinline__ unsigned short f2bf(float f) {
    __nv_bfloat16 b = __float2bfloat16(f);
    return *reinterpret_cast<unsigned short*>(&b);
}
__device__ __forceinline__ float bf2f(unsigned short u) {
    __nv_bfloat16 b;
    *reinterpret_cast<unsigned short*>(&b) = u;
    return __bfloat162float(b);
}
__device__ __forceinline__ uint32_t smem_u32(const void* p) {
    uint32_t a;
    asm("{ .reg .u64 t; cvta.to.shared.u64 t, %1; cvt.u32.u64 %0, t; }" : "=r"(a) : "l"(p));
    return a;
}

// ---------------- kernel: zero degree histogram ----------------
__global__ void k_zero() {
    int i = blockIdx.x * blockDim.x + threadIdx.x;
    if (i < N_NODES) g_deg[i] = 0;
}

// ---------------- split kernels: build A' and B' ----------------
__global__ __launch_bounds__(256) void k_split_a(const float* __restrict__ x) {
    int t = blockIdx.x * blockDim.x + threadIdx.x;  // N_NODES*128 threads, 4 elems each
    if (t >= N_NODES * 128) return;
    int m = t >> 7;
    int k4 = (t & 127) * 4;
    float4 v = *(const float4*)(x + (size_t)m * IN_CH + k4);
    unsigned short h0 = f2bf(v.x), h1 = f2bf(v.y), h2 = f2bf(v.z), h3 = f2bf(v.w);
    unsigned short l0 = f2bf(v.x - bf2f(h0)), l1 = f2bf(v.y - bf2f(h1));
    unsigned short l2 = f2bf(v.z - bf2f(h2)), l3 = f2bf(v.w - bf2f(h3));
    uint2 hi2 = make_uint2((uint32_t)h0 | ((uint32_t)h1 << 16),
                           (uint32_t)h2 | ((uint32_t)h3 << 16));
    uint2 lo2 = make_uint2((uint32_t)l0 | ((uint32_t)l1 << 16),
                           (uint32_t)l2 | ((uint32_t)l3 << 16));
    size_t base = (size_t)m * KBIG;
    *(uint2*)(g_Abig + base + k4) = hi2;          // ah
    *(uint2*)(g_Abig + base + 512 + k4) = hi2;    // ah
    *(uint2*)(g_Abig + base + 1024 + k4) = lo2;   // al
}

__global__ __launch_bounds__(256) void k_split_b(const float* __restrict__ W1) {
    int t = blockIdx.x * blockDim.x + threadIdx.x;  // 512*512
    if (t >= IN_CH * D1) return;
    int k = t >> 9;     // row of W1
    int n = t & 511;    // col of W1 -> row of B'
    float w = W1[(size_t)k * D1 + n];
    unsigned short h = f2bf(w);
    unsigned short l = f2bf(w - bf2f(h));
    size_t base = (size_t)n * KBIG;
    g_Bbig[base + k] = h;           // bh
    g_Bbig[base + 512 + k] = l;     // bl
    g_Bbig[base + 1024 + k] = h;    // bh
}

// ---------------- kernel: mma.sync bf16 GEMM  g_h1 = A' @ B'^T ----------------
// 128x128 CTA tile, 8 warps (2x4 -> 64x32 warp tile), BK=32.
// 4-stage cp.async pipeline (gmem->smem, no register staging); ldmatrix feeds.
#define TBM 128
#define TBN 128
#define TBK 32
#define TNC (KBIG / TBK)     // 48 chunks
#define ASTR (TBK + 8)       // 40 shorts/row (80B stride: conflict-free ldmatrix)
#define NSTAGE 4
#define SSZ ((TBM + TBN) * ASTR * 2)   // 20480 B per stage
#define BOFF (TBM * ASTR * 2)          // 10240 B: B tile offset within stage
#define GSMEM (NSTAGE * SSZ)           // 81920 B

__device__ __forceinline__ void mma16816(float* c, const uint32_t* a, const uint32_t* b) {
    asm volatile(
        "mma.sync.aligned.m16n8k16.row.col.f32.bf16.bf16.f32 "
        "{%0,%1,%2,%3}, {%4,%5,%6,%7}, {%8,%9}, {%0,%1,%2,%3};"
        : "+f"(c[0]), "+f"(c[1]), "+f"(c[2]), "+f"(c[3])
        : "r"(a[0]), "r"(a[1]), "r"(a[2]), "r"(a[3]), "r"(b[0]), "r"(b[1]));
}
__device__ __forceinline__ void ldsm4(uint32_t* r, uint32_t addr) {
    asm volatile("ldmatrix.sync.aligned.m8n8.x4.shared.b16 {%0,%1,%2,%3}, [%4];"
                 : "=r"(r[0]), "=r"(r[1]), "=r"(r[2]), "=r"(r[3])
                 : "r"(addr));
}
__device__ __forceinline__ void cpasync16(uint32_t dst, const void* src) {
    asm volatile("cp.async.cg.shared.global [%0], [%1], 16;" :: "r"(dst), "l"(src));
}
__device__ __forceinline__ void cp_commit() {
    asm volatile("cp.async.commit_group;" ::: "memory");
}
template <int N>
__device__ __forceinline__ void cp_wait() {
    asm volatile("cp.async.wait_group %0;" :: "n"(N) : "memory");
}

__global__ __launch_bounds__(256, 2) void k_gemm_mma() {
    extern __shared__ unsigned short smbuf[];
    const uint32_t sbase = smem_u32(smbuf);
    const int tid = threadIdx.x;
    const int wid = tid >> 5;
    const int lane = tid & 31;
    const int g = lane >> 2;   // 0..7
    const int tg = lane & 3;   // 0..3
    const int wm = (wid & 1) * 64;
    const int wn = (wid >> 1) * 32;
    const int bm = blockIdx.x * TBM;
    const int bn = blockIdx.y * TBN;

    // ldmatrix per-lane source rows/cols
    const int a_r = wm + (lane & 15);
    const int a_c = (lane >> 4) << 3;
    const int b_r = wn + (lane & 7) + ((lane & 16) >> 1);
    const int b_c = (lane & 8);

    // loader mapping: per tile 128 rows x 64B = 512 x 16B segs; 2 A + 2 B per thread
    int lrow[2], lq[2], garow[2], gbrow[2];
#pragma unroll
    for (int i = 0; i < 2; i++) {
        int s = tid + i * 256;
        lrow[i] = s >> 2;
        lq[i] = (s & 3) * 8;  // short offset of 16B seg
        int gm = bm + lrow[i];
        garow[i] = (gm < N_NODES) ? gm : (N_NODES - 1);
        gbrow[i] = bn + lrow[i];  // < 512 always
    }

    float acc[4][4][4];
#pragma unroll
    for (int mi = 0; mi < 4; mi++)
#pragma unroll
        for (int ni = 0; ni < 4; ni++)
#pragma unroll
            for (int j = 0; j < 4; j++) acc[mi][ni][j] = 0.f;

    // async load of chunk c into stage c&3
#define ISSUE(c)                                                                       \
    do {                                                                               \
        const uint32_t st_ = sbase + (uint32_t)((c) & 3) * SSZ;                        \
        const int k0_ = (c) * TBK;                                                     \
        _Pragma("unroll") for (int i = 0; i < 2; i++) {                                \
            cpasync16(st_ + (uint32_t)(lrow[i] * ASTR + lq[i]) * 2,                    \
                      g_Abig + (size_t)garow[i] * KBIG + k0_ + lq[i]);                 \
            cpasync16(st_ + BOFF + (uint32_t)(lrow[i] * ASTR + lq[i]) * 2,             \
                      g_Bbig + (size_t)gbrow[i] * KBIG + k0_ + lq[i]);                 \
        }                                                                              \
        cp_commit();                                                                   \
    } while (0)

    ISSUE(0);
    ISSUE(1);
    ISSUE(2);

    for (int c = 0; c < TNC; c++) {
        cp_wait<2>();      // chunk c resident
        __syncthreads();   // all warps done with stage (c-1)&3 and see chunk c
        if (c + 3 < TNC) ISSUE(c + 3);  // fills stage (c-1)&3, freed by barrier above
        const uint32_t aB = sbase + (uint32_t)(c & 3) * SSZ;
        const uint32_t bB = aB + BOFF;
#pragma unroll
        for (int ks = 0; ks < 2; ks++) {
            const int kb = ks * 16;
            uint32_t af[4][4], bf[4][2];
#pragma unroll
            for (int mi = 0; mi < 4; mi++) {
                ldsm4(af[mi], aB + (uint32_t)((a_r + mi * 16) * ASTR + kb + a_c) * 2);
            }
            {
                uint32_t t0[4], t1[4];
                ldsm4(t0, bB + (uint32_t)((b_r) * ASTR + kb + b_c) * 2);       // ni 0,1
                ldsm4(t1, bB + (uint32_t)((b_r + 16) * ASTR + kb + b_c) * 2);  // ni 2,3
                bf[0][0] = t0[0]; bf[0][1] = t0[1];
                bf[1][0] = t0[2]; bf[1][1] = t0[3];
                bf[2][0] = t1[0]; bf[2][1] = t1[1];
                bf[3][0] = t1[2]; bf[3][1] = t1[3];
            }
#pragma unroll
            for (int mi = 0; mi < 4; mi++)
#pragma unroll
                for (int ni = 0; ni < 4; ni++) mma16816(acc[mi][ni], af[mi], bf[ni]);
        }
    }
#undef ISSUE

    // epilogue: frag (mi,ni): c0,c1 -> (row, col..col+1), c2,c3 -> (row+8, ...)
#pragma unroll
    for (int mi = 0; mi < 4; mi++) {
        const int r0 = bm + wm + mi * 16 + g;
#pragma unroll
        for (int ni = 0; ni < 4; ni++) {
            const int col = bn + wn + ni * 8 + tg * 2;
            if (r0 < N_NODES)
                *(float2*)(g_h1 + (size_t)r0 * D1 + col) = make_float2(acc[mi][ni][0], acc[mi][ni][1]);
            if (r0 + 8 < N_NODES)
                *(float2*)(g_h1 + (size_t)(r0 + 8) * D1 + col) = make_float2(acc[mi][ni][2], acc[mi][ni][3]);
        }
    }
}

// ---------------- kernel: per-node attention scalars a_src1/a_dst1 ----------------
__global__ void k_att1(const float* __restrict__ as1, const float* __restrict__ ad1) {
    int n = blockIdx.x;
    int h = threadIdx.x >> 5;
    int lane = threadIdx.x & 31;
    float4 hv = ((const float4*)g_h1)[(size_t)n * 128 + h * 32 + lane];
    float4 sa = ((const float4*)as1)[h * 32 + lane];
    float4 da = ((const float4*)ad1)[h * 32 + lane];
    float s = hv.x * sa.x + hv.y * sa.y + hv.z * sa.z + hv.w * sa.w;
    float d = hv.x * da.x + hv.y * da.y + hv.z * da.z + hv.w * da.w;
#pragma unroll
    for (int o = 16; o > 0; o >>= 1) {
        s += __shfl_xor_sync(0xffffffffu, s, o);
        d += __shfl_xor_sync(0xffffffffu, d, o);
    }
    if (lane == 0) {
        g_asrc1[n * HEADS + h] = s;
        g_adst1[n * HEADS + h] = d;
    }
}

// ---------------- CSR build: histogram / scan / scatter ----------------
__global__ void k_hist(const int* __restrict__ ei) {
    int e = blockIdx.x * blockDim.x + threadIdx.x;
    if (e >= E2) return;
    int dst = (e < N_EDGES) ? ei[N_EDGES + e] : (e - N_EDGES);
    atomicAdd(&g_deg[dst], 1);
}

__global__ void k_scan() {
    __shared__ int part[1024];
    const int tid = threadIdx.x;
    const int CH = (N_NODES + 1023) / 1024;  // 10
    int base = tid * CH;
    int s = 0;
    for (int i = 0; i < CH; i++) {
        int idx = base + i;
        if (idx < N_NODES) s += g_deg[idx];
    }
    part[tid] = s;
    __syncthreads();
    for (int off = 1; off < 1024; off <<= 1) {
        int v = (tid >= off) ? part[tid - off] : 0;
        __syncthreads();
        part[tid] += v;
        __syncthreads();
    }
    int run = (tid == 0) ? 0 : part[tid - 1];
    for (int i = 0; i < CH; i++) {
        int idx = base + i;
        if (idx < N_NODES) {
            g_row[idx] = run;
            g_cur[idx] = run;
            run += g_deg[idx];
        }
    }
    if (tid == 1023) g_row[N_NODES] = part[1023];
}

__global__ void k_scatter(const int* __restrict__ ei) {
    int e = blockIdx.x * blockDim.x + threadIdx.x;
    if (e >= E2) return;
    int src, dst;
    if (e < N_EDGES) {
        src = ei[e];
        dst = ei[N_EDGES + e];
    } else {
        src = dst = e - N_EDGES;
    }
    int p = atomicAdd(&g_cur[dst], 1);
    g_csr[p] = src;
}

// ---------------- kernel: layer-1 softmax-aggregate + bias + ELU ----------------
// one 128-thread CTA per dst node; thread t owns channels [4t, 4t+4); head = t/32.
__global__ __launch_bounds__(128) void k_agg1(const float* __restrict__ b1) {
    const int n = blockIdx.x;
    const int tid = threadIdx.x;
    __shared__ float4 red[128];
    __shared__ float s_ad[4];
    if (tid < 4) s_ad[tid] = g_adst1[n * HEADS + tid];
    __syncthreads();
    const int beg = g_row[n];
    const int end = g_row[n + 1];
    const float a0 = s_ad[0], a1 = s_ad[1], a2 = s_ad[2], a3 = s_ad[3];

    float4 mx = make_float4(-INFINITY, -INFINITY, -INFINITY, -INFINITY);
    for (int k = beg + tid; k < end; k += 128) {
        int s = g_csr[k];
        const float* as = &g_asrc1[s * HEADS];
        mx.x = fmaxf(mx.x, lrelu(as[0] + a0));
        mx.y = fmaxf(mx.y, lrelu(as[1] + a1));
        mx.z = fmaxf(mx.z, lrelu(as[2] + a2));
        mx.w = fmaxf(mx.w, lrelu(as[3] + a3));
    }
    red[tid] = mx;
    __syncthreads();
#pragma unroll
    for (int off = 64; off > 0; off >>= 1) {
        if (tid < off) {
            float4 u = red[tid], v = red[tid + off];
            u.x = fmaxf(u.x, v.x);
            u.y = fmaxf(u.y, v.y);
            u.z = fmaxf(u.z, v.z);
            u.w = fmaxf(u.w, v.w);
            red[tid] = u;
        }
        __syncthreads();
    }
    const float4 M4 = red[0];

    const int h = tid >> 5;
    const float mh = (h == 0) ? M4.x : (h == 1) ? M4.y : (h == 2) ? M4.z : M4.w;
    const float ah = (h == 0) ? a0 : (h == 1) ? a1 : (h == 2) ? a2 : a3;

    // pass B: 2-way unrolled edge walk (MLP=2 on the 16B row loads)
    const float4* h1v = (const float4*)g_h1;
    float4 acc = make_float4(0.f, 0.f, 0.f, 0.f);
    float den = 0.f;
    int k = beg;
    for (; k + 2 <= end; k += 2) {
        int sA = g_csr[k];
        int sB = g_csr[k + 1];
        float eA = lrelu(g_asrc1[sA * HEADS + h] + ah);
        float eB = lrelu(g_asrc1[sB * HEADS + h] + ah);
        float4 hvA = h1v[(size_t)sA * 128 + tid];
        float4 hvB = h1v[(size_t)sB * 128 + tid];
        float exA = expf(eA - mh);
        float exB = expf(eB - mh);
        den += exA + exB;
        acc.x = fmaf(exA, hvA.x, acc.x);
        acc.y = fmaf(exA, hvA.y, acc.y);
        acc.z = fmaf(exA, hvA.z, acc.z);
        acc.w = fmaf(exA, hvA.w, acc.w);
        acc.x = fmaf(exB, hvB.x, acc.x);
        acc.y = fmaf(exB, hvB.y, acc.y);
        acc.z = fmaf(exB, hvB.z, acc.z);
        acc.w = fmaf(exB, hvB.w, acc.w);
    }
    if (k < end) {
        int s = g_csr[k];
        float e = lrelu(g_asrc1[s * HEADS + h] + ah);
        float ex = expf(e - mh);
        den += ex;
        float4 hv = h1v[(size_t)s * 128 + tid];
        acc.x = fmaf(ex, hv.x, acc.x);
        acc.y = fmaf(ex, hv.y, acc.y);
        acc.z = fmaf(ex, hv.z, acc.z);
        acc.w = fmaf(ex, hv.w, acc.w);
    }
    const float inv = 1.f / (den + 1e-16f);
    float4 bb = ((const float4*)b1)[tid];
    float o0 = acc.x * inv + bb.x;
    float o1 = acc.y * inv + bb.y;
    float o2 = acc.z * inv + bb.z;
    float o3 = acc.w * inv + bb.w;
    o0 = o0 > 0.f ? o0 : expm1f(o0);
    o1 = o1 > 0.f ? o1 : expm1f(o1);
    o2 = o2 > 0.f ? o2 : expm1f(o2);
    o3 = o3 > 0.f ? o3 : expm1f(o3);
    ((float4*)g_act1)[(size_t)n * 128 + tid] = make_float4(o0, o1, o2, o3);
}

// ---------------- kernel: layer-2 GEMV (512->2) + attention scalars ----------------
__global__ __launch_bounds__(128) void k_l2(const float* __restrict__ W2,
                                            const float* __restrict__ as2,
                                            const float* __restrict__ ad2) {
    const int n = blockIdx.x;
    const int tid = threadIdx.x;
    __shared__ float2 red[128];
    float4 a = ((const float4*)g_act1)[(size_t)n * 128 + tid];
    float4 w01 = ((const float4*)W2)[tid * 2];
    float4 w23 = ((const float4*)W2)[tid * 2 + 1];
    float s0 = a.x * w01.x + a.y * w01.z + a.z * w23.x + a.w * w23.z;
    float s1 = a.x * w01.y + a.y * w01.w + a.z * w23.y + a.w * w23.w;
    red[tid] = make_float2(s0, s1);
    __syncthreads();
#pragma unroll
    for (int off = 64; off > 0; off >>= 1) {
        if (tid < off) {
            red[tid].x += red[tid + off].x;
            red[tid].y += red[tid + off].y;
        }
        __syncthreads();
    }
    if (tid == 0) {
        float h0 = red[0].x, h1 = red[0].y;
        g_h2[n * 2] = h0;
        g_h2[n * 2 + 1] = h1;
        g_asrc2[n] = h0 * as2[0] + h1 * as2[1];
        g_adst2[n] = h0 * ad2[0] + h1 * ad2[1];
    }
}

// ---------------- kernel: layer-2 aggregate (one warp per node) ----------------
__global__ __launch_bounds__(128) void k_agg2(const float* __restrict__ b2,
                                              float* __restrict__ out) {
    const int warp = threadIdx.x >> 5;
    const int lane = threadIdx.x & 31;
    const int n = blockIdx.x * 4 + warp;
    if (n >= N_NODES) return;
    const int beg = g_row[n];
    const int end = g_row[n + 1];
    const float ad = g_adst2[n];

    float mx = -INFINITY;
    for (int k = beg + lane; k < end; k += 32)
        mx = fmaxf(mx, lrelu(g_asrc2[g_csr[k]] + ad));
#pragma unroll
    for (int o = 16; o > 0; o >>= 1) mx = fmaxf(mx, __shfl_xor_sync(0xffffffffu, mx, o));

    float den = 0.f, c0 = 0.f, c1 = 0.f;
    for (int k = beg + lane; k < end; k += 32) {
        int s = g_csr[k];
        float e = lrelu(g_asrc2[s] + ad);
        float ex = expf(e - mx);
        den += ex;
        float2 hv = ((const float2*)g_h2)[s];
        c0 = fmaf(ex, hv.x, c0);
        c1 = fmaf(ex, hv.y, c1);
    }
#pragma unroll
    for (int o = 16; o > 0; o >>= 1) {
        den += __shfl_xor_sync(0xffffffffu, den, o);
        c0 += __shfl_xor_sync(0xffffffffu, c0, o);
        c1 += __shfl_xor_sync(0xffffffffu, c1, o);
    }
    if (lane == 0) {
        float inv = 1.f / (den + 1e-16f);
        out[n * 2] = c0 * inv + b2[0];
        out[n * 2 + 1] = c1 * inv + b2[1];
    }
}

// ---------------- launch: CSR build forked onto side stream (hidden under GEMM) ----
extern "C" void kernel_launch(void* const* d_in, const int* in_sizes, int n_in,
                              void* d_out, int out_size) {
    const float* x   = (const float*)d_in[0];
    const int*   ei  = (const int*)d_in[1];
    const float* W1  = (const float*)d_in[2];
    const float* as1 = (const float*)d_in[3];
    const float* ad1 = (const float*)d_in[4];
    const float* b1  = (const float*)d_in[5];
    const float* W2  = (const float*)d_in[6];
    const float* as2 = (const float*)d_in[7];
    const float* ad2 = (const float*)d_in[8];
    const float* b2  = (const float*)d_in[9];
    float* out = (float*)d_out;

    cudaFuncSetAttribute(k_gemm_mma, cudaFuncAttributeMaxDynamicSharedMemorySize, GSMEM);

    static cudaStream_t s2 = nullptr;
    static cudaEvent_t evF = nullptr, evJ = nullptr;
    if (s2 == nullptr) {
        cudaStreamCreateWithFlags(&s2, cudaStreamNonBlocking);
        cudaEventCreateWithFlags(&evF, cudaEventDisableTiming);
        cudaEventCreateWithFlags(&evJ, cudaEventDisableTiming);
    }

    // fork: CSR build (independent of the dense chain) on s2
    cudaEventRecord(evF, 0);
    cudaStreamWaitEvent(s2, evF, 0);
    k_zero<<<(N_NODES + 255) / 256, 256, 0, s2>>>();
    k_hist<<<(E2 + 255) / 256, 256, 0, s2>>>(ei);
    k_scan<<<1, 1024, 0, s2>>>();
    k_scatter<<<(E2 + 255) / 256, 256, 0, s2>>>(ei);
    cudaEventRecord(evJ, s2);

    // main: dense pipeline
    k_split_a<<<(N_NODES * 128 + 255) / 256, 256>>>(x);
    k_split_b<<<(IN_CH * D1 + 255) / 256, 256>>>(W1);
    k_gemm_mma<<<dim3((N_NODES + TBM - 1) / TBM, D1 / TBN), 256, GSMEM>>>();
    k_att1<<<N_NODES, 128>>>(as1, ad1);

    // join: agg1 needs h1/att scalars AND the CSR
    cudaStreamWaitEvent(0, evJ, 0);
    k_agg1<<<N_NODES, 128>>>(b1);
    k_l2<<<N_NODES, 128>>>(W2, as2, ad2);
    k_agg2<<<(N_NODES + 3) / 4, 128>>>(b2, out);
}

// round 17
// speedup vs baseline: 1.5068x; 1.0216x over previous
#include <cuda_runtime.h>
#include <cuda_bf16.h>
#include <math.h>
#include <stdint.h>

#define N_NODES 10000
#define N_EDGES 320000
#define E2      (N_EDGES + N_NODES)   // + self loops
#define IN_CH   512
#define D1      512                   // HEADS * HID
#define HEADS   4
#define HID     128
#define NEG_SLOPE 0.2f
#define KBIG    1536                  // 3 * 512 (split-K trick)

// ---------------- scratch (no allocations allowed) ----------------
__device__ __align__(16) float g_h1  [N_NODES * D1];   // x @ W1 (fp32 result)
__device__ __align__(16) float g_act1[N_NODES * D1];   // elu(agg1 + b1)
__device__ float g_asrc1[N_NODES * HEADS];
__device__ float g_adst1[N_NODES * HEADS];
__device__ __align__(16) float g_h2[N_NODES * 2];
__device__ float g_asrc2[N_NODES];
__device__ float g_adst2[N_NODES];
__device__ int g_deg[N_NODES];
__device__ int g_row[N_NODES + 1];
__device__ int g_cur[N_NODES];
__device__ int g_csr[E2];
// split operands: A' = [ah | ah | al] (rows=M, K'=1536), B' = [bh | bl | bh] (rows=N=512)
__device__ __align__(16) unsigned short g_Abig[(size_t)N_NODES * KBIG];  // 30.7 MB bf16
__device__ __align__(16) unsigned short g_Bbig[(size_t)D1 * KBIG];      // 1.6 MB bf16

// ---------------- helpers ----------------
__device__ __forceinline__ float lrelu(float e) { return e > 0.f ? e : NEG_SLOPE * e; }

__device__ __forceinline__ unsigned short f2bf(float f) {
    __nv_bfloat16 b = __float2bfloat16(f);
    return *reinterpret_cast<unsigned short*>(&b);
}
__device__ __forceinline__ float bf2f(unsigned short u) {
    __nv_bfloat16 b;
    *reinterpret_cast<unsigned short*>(&b) = u;
    return __bfloat162float(b);
}
__device__ __forceinline__ uint32_t smem_u32(const void* p) {
    uint32_t a;
    asm("{ .reg .u64 t; cvta.to.shared.u64 t, %1; cvt.u32.u64 %0, t; }" : "=r"(a) : "l"(p));
    return a;
}

// ---------------- kernel: zero degree histogram ----------------
__global__ void k_zero() {
    int i = blockIdx.x * blockDim.x + threadIdx.x;
    if (i < N_NODES) g_deg[i] = 0;
}

// ---------------- split kernels: build A' and B' ----------------
__global__ __launch_bounds__(256) void k_split_a(const float* __restrict__ x) {
    int t = blockIdx.x * blockDim.x + threadIdx.x;  // N_NODES*128 threads, 4 elems each
    if (t >= N_NODES * 128) return;
    int m = t >> 7;
    int k4 = (t & 127) * 4;
    float4 v = *(const float4*)(x + (size_t)m * IN_CH + k4);
    unsigned short h0 = f2bf(v.x), h1 = f2bf(v.y), h2 = f2bf(v.z), h3 = f2bf(v.w);
    unsigned short l0 = f2bf(v.x - bf2f(h0)), l1 = f2bf(v.y - bf2f(h1));
    unsigned short l2 = f2bf(v.z - bf2f(h2)), l3 = f2bf(v.w - bf2f(h3));
    uint2 hi2 = make_uint2((uint32_t)h0 | ((uint32_t)h1 << 16),
                           (uint32_t)h2 | ((uint32_t)h3 << 16));
    uint2 lo2 = make_uint2((uint32_t)l0 | ((uint32_t)l1 << 16),
                           (uint32_t)l2 | ((uint32_t)l3 << 16));
    size_t base = (size_t)m * KBIG;
    *(uint2*)(g_Abig + base + k4) = hi2;          // ah
    *(uint2*)(g_Abig + base + 512 + k4) = hi2;    // ah
    *(uint2*)(g_Abig + base + 1024 + k4) = lo2;   // al
}

__global__ __launch_bounds__(256) void k_split_b(const float* __restrict__ W1) {
    int t = blockIdx.x * blockDim.x + threadIdx.x;  // 512*512
    if (t >= IN_CH * D1) return;
    int k = t >> 9;     // row of W1
    int n = t & 511;    // col of W1 -> row of B'
    float w = W1[(size_t)k * D1 + n];
    unsigned short h = f2bf(w);
    unsigned short l = f2bf(w - bf2f(h));
    size_t base = (size_t)n * KBIG;
    g_Bbig[base + k] = h;           // bh
    g_Bbig[base + 512 + k] = l;     // bl
    g_Bbig[base + 1024 + k] = h;    // bh
}

// ---------------- kernel: mma.sync bf16 GEMM  g_h1 = A' @ B'^T ----------------
// 128x64 CTA tile, 8 warps (2x4 -> 64x16 warp tile), BK=32, 3 CTAs/SM.
// 4-stage cp.async pipeline; ldmatrix feeds (80B row stride: conflict-free).
#define TBM 128
#define TBN 64
#define TBK 32
#define TNC (KBIG / TBK)     // 48 chunks
#define ASTR (TBK + 8)       // 40 shorts/row
#define NSTAGE 4
#define SSZ ((TBM + TBN) * ASTR * 2)   // 15360 B per stage
#define BOFF (TBM * ASTR * 2)          // 10240 B: B tile offset within stage
#define GSMEM (NSTAGE * SSZ)           // 61440 B

__device__ __forceinline__ void mma16816(float* c, const uint32_t* a, const uint32_t* b) {
    asm volatile(
        "mma.sync.aligned.m16n8k16.row.col.f32.bf16.bf16.f32 "
        "{%0,%1,%2,%3}, {%4,%5,%6,%7}, {%8,%9}, {%0,%1,%2,%3};"
        : "+f"(c[0]), "+f"(c[1]), "+f"(c[2]), "+f"(c[3])
        : "r"(a[0]), "r"(a[1]), "r"(a[2]), "r"(a[3]), "r"(b[0]), "r"(b[1]));
}
__device__ __forceinline__ void ldsm4(uint32_t* r, uint32_t addr) {
    asm volatile("ldmatrix.sync.aligned.m8n8.x4.shared.b16 {%0,%1,%2,%3}, [%4];"
                 : "=r"(r[0]), "=r"(r[1]), "=r"(r[2]), "=r"(r[3])
                 : "r"(addr));
}
__device__ __forceinline__ void cpasync16(uint32_t dst, const void* src) {
    asm volatile("cp.async.cg.shared.global [%0], [%1], 16;" :: "r"(dst), "l"(src));
}
__device__ __forceinline__ void cp_commit() {
    asm volatile("cp.async.commit_group;" ::: "memory");
}
template <int N>
__device__ __forceinline__ void cp_wait() {
    asm volatile("cp.async.wait_group %0;" :: "n"(N) : "memory");
}

__global__ __launch_bounds__(256, 3) void k_gemm_mma() {
    extern __shared__ unsigned short smbuf[];
    const uint32_t sbase = smem_u32(smbuf);
    const int tid = threadIdx.x;
    const int wid = tid >> 5;
    const int lane = tid & 31;
    const int g = lane >> 2;   // 0..7
    const int tg = lane & 3;   // 0..3
    const int wm = (wid & 1) * 64;   // 2 warps over M=128
    const int wn = (wid >> 1) * 16;  // 4 warps over N=64
    const int bm = blockIdx.x * TBM;
    const int bn = blockIdx.y * TBN;

    // ldmatrix per-lane source rows/cols (A unchanged; B covers 16 n-rows, ni=0,1)
    const int a_r = wm + (lane & 15);
    const int a_c = (lane >> 4) << 3;
    const int b_r = wn + (lane & 7) + ((lane & 16) >> 1);
    const int b_c = (lane & 8);

    // loader: per stage 128 A rows + 64 B rows, 64B each; 3 x 16B segs per thread
    const int lr = tid >> 2;           // 0..63
    const int lq = (tid & 3) * 8;      // short offset of 16B seg
    int ga0 = bm + lr;        if (ga0 >= N_NODES) ga0 = N_NODES - 1;
    int ga1 = bm + 64 + lr;   if (ga1 >= N_NODES) ga1 = N_NODES - 1;
    const int gb = bn + lr;   // < 512 always

    float acc[4][2][4];
#pragma unroll
    for (int mi = 0; mi < 4; mi++)
#pragma unroll
        for (int ni = 0; ni < 2; ni++)
#pragma unroll
            for (int j = 0; j < 4; j++) acc[mi][ni][j] = 0.f;

    // async load of chunk c into stage c&3
#define ISSUE(c)                                                                       \
    do {                                                                               \
        const uint32_t st_ = sbase + (uint32_t)((c) & 3) * SSZ;                        \
        const int k0_ = (c) * TBK;                                                     \
        cpasync16(st_ + (uint32_t)(lr * ASTR + lq) * 2,                                \
                  g_Abig + (size_t)ga0 * KBIG + k0_ + lq);                             \
        cpasync16(st_ + (uint32_t)((64 + lr) * ASTR + lq) * 2,                         \
                  g_Abig + (size_t)ga1 * KBIG + k0_ + lq);                             \
        cpasync16(st_ + BOFF + (uint32_t)(lr * ASTR + lq) * 2,                         \
                  g_Bbig + (size_t)gb * KBIG + k0_ + lq);                              \
        cp_commit();                                                                   \
    } while (0)

    ISSUE(0);
    ISSUE(1);
    ISSUE(2);

    for (int c = 0; c < TNC; c++) {
        cp_wait<2>();      // chunk c resident
        __syncthreads();   // all warps done with stage (c-1)&3 and see chunk c
        if (c + 3 < TNC) ISSUE(c + 3);  // fills stage (c-1)&3, freed by barrier above
        const uint32_t aB = sbase + (uint32_t)(c & 3) * SSZ;
        const uint32_t bB = aB + BOFF;
#pragma unroll
        for (int ks = 0; ks < 2; ks++) {
            const int kb = ks * 16;
            uint32_t af[4][4], bf[2][2];
#pragma unroll
            for (int mi = 0; mi < 4; mi++) {
                ldsm4(af[mi], aB + (uint32_t)((a_r + mi * 16) * ASTR + kb + a_c) * 2);
            }
            {
                uint32_t t0[4];
                ldsm4(t0, bB + (uint32_t)((b_r) * ASTR + kb + b_c) * 2);  // ni 0,1
                bf[0][0] = t0[0]; bf[0][1] = t0[1];
                bf[1][0] = t0[2]; bf[1][1] = t0[3];
            }
#pragma unroll
            for (int mi = 0; mi < 4; mi++)
#pragma unroll
                for (int ni = 0; ni < 2; ni++) mma16816(acc[mi][ni], af[mi], bf[ni]);
        }
    }
#undef ISSUE

    // epilogue: frag (mi,ni): c0,c1 -> (row, col..col+1), c2,c3 -> (row+8, ...)
#pragma unroll
    for (int mi = 0; mi < 4; mi++) {
        const int r0 = bm + wm + mi * 16 + g;
#pragma unroll
        for (int ni = 0; ni < 2; ni++) {
            const int col = bn + wn + ni * 8 + tg * 2;
            if (r0 < N_NODES)
                *(float2*)(g_h1 + (size_t)r0 * D1 + col) = make_float2(acc[mi][ni][0], acc[mi][ni][1]);
            if (r0 + 8 < N_NODES)
                *(float2*)(g_h1 + (size_t)(r0 + 8) * D1 + col) = make_float2(acc[mi][ni][2], acc[mi][ni][3]);
        }
    }
}

// ---------------- kernel: per-node attention scalars a_src1/a_dst1 ----------------
__global__ void k_att1(const float* __restrict__ as1, const float* __restrict__ ad1) {
    int n = blockIdx.x;
    int h = threadIdx.x >> 5;
    int lane = threadIdx.x & 31;
    float4 hv = ((const float4*)g_h1)[(size_t)n * 128 + h * 32 + lane];
    float4 sa = ((const float4*)as1)[h * 32 + lane];
    float4 da = ((const float4*)ad1)[h * 32 + lane];
    float s = hv.x * sa.x + hv.y * sa.y + hv.z * sa.z + hv.w * sa.w;
    float d = hv.x * da.x + hv.y * da.y + hv.z * da.z + hv.w * da.w;
#pragma unroll
    for (int o = 16; o > 0; o >>= 1) {
        s += __shfl_xor_sync(0xffffffffu, s, o);
        d += __shfl_xor_sync(0xffffffffu, d, o);
    }
    if (lane == 0) {
        g_asrc1[n * HEADS + h] = s;
        g_adst1[n * HEADS + h] = d;
    }
}

// ---------------- CSR build: histogram / scan / scatter ----------------
__global__ void k_hist(const int* __restrict__ ei) {
    int e = blockIdx.x * blockDim.x + threadIdx.x;
    if (e >= E2) return;
    int dst = (e < N_EDGES) ? ei[N_EDGES + e] : (e - N_EDGES);
    atomicAdd(&g_deg[dst], 1);
}

__global__ void k_scan() {
    __shared__ int part[1024];
    const int tid = threadIdx.x;
    const int CH = (N_NODES + 1023) / 1024;  // 10
    int base = tid * CH;
    int s = 0;
    for (int i = 0; i < CH; i++) {
        int idx = base + i;
        if (idx < N_NODES) s += g_deg[idx];
    }
    part[tid] = s;
    __syncthreads();
    for (int off = 1; off < 1024; off <<= 1) {
        int v = (tid >= off) ? part[tid - off] : 0;
        __syncthreads();
        part[tid] += v;
        __syncthreads();
    }
    int run = (tid == 0) ? 0 : part[tid - 1];
    for (int i = 0; i < CH; i++) {
        int idx = base + i;
        if (idx < N_NODES) {
            g_row[idx] = run;
            g_cur[idx] = run;
            run += g_deg[idx];
        }
    }
    if (tid == 1023) g_row[N_NODES] = part[1023];
}

__global__ void k_scatter(const int* __restrict__ ei) {
    int e = blockIdx.x * blockDim.x + threadIdx.x;
    if (e >= E2) return;
    int src, dst;
    if (e < N_EDGES) {
        src = ei[e];
        dst = ei[N_EDGES + e];
    } else {
        src = dst = e - N_EDGES;
    }
    int p = atomicAdd(&g_cur[dst], 1);
    g_csr[p] = src;
}

// ---------------- kernel: layer-1 softmax-aggregate + bias + ELU ----------------
// one 128-thread CTA per dst node; thread t owns channels [4t, 4t+4); head = t/32.
__global__ __launch_bounds__(128) void k_agg1(const float* __restrict__ b1) {
    const int n = blockIdx.x;
    const int tid = threadIdx.x;
    __shared__ float4 red[128];
    __shared__ float s_ad[4];
    if (tid < 4) s_ad[tid] = g_adst1[n * HEADS + tid];
    __syncthreads();
    const int beg = g_row[n];
    const int end = g_row[n + 1];
    const float a0 = s_ad[0], a1 = s_ad[1], a2 = s_ad[2], a3 = s_ad[3];

    float4 mx = make_float4(-INFINITY, -INFINITY, -INFINITY, -INFINITY);
    for (int k = beg + tid; k < end; k += 128) {
        int s = g_csr[k];
        const float* as = &g_asrc1[s * HEADS];
        mx.x = fmaxf(mx.x, lrelu(as[0] + a0));
        mx.y = fmaxf(mx.y, lrelu(as[1] + a1));
        mx.z = fmaxf(mx.z, lrelu(as[2] + a2));
        mx.w = fmaxf(mx.w, lrelu(as[3] + a3));
    }
    red[tid] = mx;
    __syncthreads();
#pragma unroll
    for (int off = 64; off > 0; off >>= 1) {
        if (tid < off) {
            float4 u = red[tid], v = red[tid + off];
            u.x = fmaxf(u.x, v.x);
            u.y = fmaxf(u.y, v.y);
            u.z = fmaxf(u.z, v.z);
            u.w = fmaxf(u.w, v.w);
            red[tid] = u;
        }
        __syncthreads();
    }
    const float4 M4 = red[0];

    const int h = tid >> 5;
    const float mh = (h == 0) ? M4.x : (h == 1) ? M4.y : (h == 2) ? M4.z : M4.w;
    const float ah = (h == 0) ? a0 : (h == 1) ? a1 : (h == 2) ? a2 : a3;

    // pass B: 2-way unrolled edge walk (MLP=2 on the 16B row loads)
    const float4* h1v = (const float4*)g_h1;
    float4 acc = make_float4(0.f, 0.f, 0.f, 0.f);
    float den = 0.f;
    int k = beg;
    for (; k + 2 <= end; k += 2) {
        int sA = g_csr[k];
        int sB = g_csr[k + 1];
        float eA = lrelu(g_asrc1[sA * HEADS + h] + ah);
        float eB = lrelu(g_asrc1[sB * HEADS + h] + ah);
        float4 hvA = h1v[(size_t)sA * 128 + tid];
        float4 hvB = h1v[(size_t)sB * 128 + tid];
        float exA = expf(eA - mh);
        float exB = expf(eB - mh);
        den += exA + exB;
        acc.x = fmaf(exA, hvA.x, acc.x);
        acc.y = fmaf(exA, hvA.y, acc.y);
        acc.z = fmaf(exA, hvA.z, acc.z);
        acc.w = fmaf(exA, hvA.w, acc.w);
        acc.x = fmaf(exB, hvB.x, acc.x);
        acc.y = fmaf(exB, hvB.y, acc.y);
        acc.z = fmaf(exB, hvB.z, acc.z);
        acc.w = fmaf(exB, hvB.w, acc.w);
    }
    if (k < end) {
        int s = g_csr[k];
        float e = lrelu(g_asrc1[s * HEADS + h] + ah);
        float ex = expf(e - mh);
        den += ex;
        float4 hv = h1v[(size_t)s * 128 + tid];
        acc.x = fmaf(ex, hv.x, acc.x);
        acc.y = fmaf(ex, hv.y, acc.y);
        acc.z = fmaf(ex, hv.z, acc.z);
        acc.w = fmaf(ex, hv.w, acc.w);
    }
    const float inv = 1.f / (den + 1e-16f);
    float4 bb = ((const float4*)b1)[tid];
    float o0 = acc.x * inv + bb.x;
    float o1 = acc.y * inv + bb.y;
    float o2 = acc.z * inv + bb.z;
    float o3 = acc.w * inv + bb.w;
    o0 = o0 > 0.f ? o0 : expm1f(o0);
    o1 = o1 > 0.f ? o1 : expm1f(o1);
    o2 = o2 > 0.f ? o2 : expm1f(o2);
    o3 = o3 > 0.f ? o3 : expm1f(o3);
    ((float4*)g_act1)[(size_t)n * 128 + tid] = make_float4(o0, o1, o2, o3);
}

// ---------------- kernel: layer-2 GEMV (512->2) + attention scalars ----------------
__global__ __launch_bounds__(128) void k_l2(const float* __restrict__ W2,
                                            const float* __restrict__ as2,
                                            const float* __restrict__ ad2) {
    const int n = blockIdx.x;
    const int tid = threadIdx.x;
    __shared__ float2 red[128];
    float4 a = ((const float4*)g_act1)[(size_t)n * 128 + tid];
    float4 w01 = ((const float4*)W2)[tid * 2];
    float4 w23 = ((const float4*)W2)[tid * 2 + 1];
    float s0 = a.x * w01.x + a.y * w01.z + a.z * w23.x + a.w * w23.z;
    float s1 = a.x * w01.y + a.y * w01.w + a.z * w23.y + a.w * w23.w;
    red[tid] = make_float2(s0, s1);
    __syncthreads();
#pragma unroll
    for (int off = 64; off > 0; off >>= 1) {
        if (tid < off) {
            red[tid].x += red[tid + off].x;
            red[tid].y += red[tid + off].y;
        }
        __syncthreads();
    }
    if (tid == 0) {
        float h0 = red[0].x, h1 = red[0].y;
        g_h2[n * 2] = h0;
        g_h2[n * 2 + 1] = h1;
        g_asrc2[n] = h0 * as2[0] + h1 * as2[1];
        g_adst2[n] = h0 * ad2[0] + h1 * ad2[1];
    }
}

// ---------------- kernel: layer-2 aggregate (one warp per node) ----------------
__global__ __launch_bounds__(128) void k_agg2(const float* __restrict__ b2,
                                              float* __restrict__ out) {
    const int warp = threadIdx.x >> 5;
    const int lane = threadIdx.x & 31;
    const int n = blockIdx.x * 4 + warp;
    if (n >= N_NODES) return;
    const int beg = g_row[n];
    const int end = g_row[n + 1];
    const float ad = g_adst2[n];

    float mx = -INFINITY;
    for (int k = beg + lane; k < end; k += 32)
        mx = fmaxf(mx, lrelu(g_asrc2[g_csr[k]] + ad));
#pragma unroll
    for (int o = 16; o > 0; o >>= 1) mx = fmaxf(mx, __shfl_xor_sync(0xffffffffu, mx, o));

    float den = 0.f, c0 = 0.f, c1 = 0.f;
    for (int k = beg + lane; k < end; k += 32) {
        int s = g_csr[k];
        float e = lrelu(g_asrc2[s] + ad);
        float ex = expf(e - mx);
        den += ex;
        float2 hv = ((const float2*)g_h2)[s];
        c0 = fmaf(ex, hv.x, c0);
        c1 = fmaf(ex, hv.y, c1);
    }
#pragma unroll
    for (int o = 16; o > 0; o >>= 1) {
        den += __shfl_xor_sync(0xffffffffu, den, o);
        c0 += __shfl_xor_sync(0xffffffffu, c0, o);
        c1 += __shfl_xor_sync(0xffffffffu, c1, o);
    }
    if (lane == 0) {
        float inv = 1.f / (den + 1e-16f);
        out[n * 2] = c0 * inv + b2[0];
        out[n * 2 + 1] = c1 * inv + b2[1];
    }
}

// ---------------- launch: CSR build forked onto side stream (hidden under GEMM) ----
extern "C" void kernel_launch(void* const* d_in, const int* in_sizes, int n_in,
                              void* d_out, int out_size) {
    const float* x   = (const float*)d_in[0];
    const int*   ei  = (const int*)d_in[1];
    const float* W1  = (const float*)d_in[2];
    const float* as1 = (const float*)d_in[3];
    const float* ad1 = (const float*)d_in[4];
    const float* b1  = (const float*)d_in[5];
    const float* W2  = (const float*)d_in[6];
    const float* as2 = (const float*)d_in[7];
    const float* ad2 = (const float*)d_in[8];
    const float* b2  = (const float*)d_in[9];
    float* out = (float*)d_out;

    cudaFuncSetAttribute(k_gemm_mma, cudaFuncAttributeMaxDynamicSharedMemorySize, GSMEM);

    static cudaStream_t s2 = nullptr;
    static cudaEvent_t evF = nullptr, evJ = nullptr;
    if (s2 == nullptr) {
        cudaStreamCreateWithFlags(&s2, cudaStreamNonBlocking);
        cudaEventCreateWithFlags(&evF, cudaEventDisableTiming);
        cudaEventCreateWithFlags(&evJ, cudaEventDisableTiming);
    }

    // fork: CSR build (independent of the dense chain) on s2
    cudaEventRecord(evF, 0);
    cudaStreamWaitEvent(s2, evF, 0);
    k_zero<<<(N_NODES + 255) / 256, 256, 0, s2>>>();
    k_hist<<<(E2 + 255) / 256, 256, 0, s2>>>(ei);
    k_scan<<<1, 1024, 0, s2>>>();
    k_scatter<<<(E2 + 255) / 256, 256, 0, s2>>>(ei);
    cudaEventRecord(evJ, s2);

    // main: dense pipeline
    k_split_a<<<(N_NODES * 128 + 255) / 256, 256>>>(x);
    k_split_b<<<(IN_CH * D1 + 255) / 256, 256>>>(W1);
    k_gemm_mma<<<dim3((N_NODES + TBM - 1) / TBM, D1 / TBN), 256, GSMEM>>>();
    k_att1<<<N_NODES, 128>>>(as1, ad1);

    // join: agg1 needs h1/att scalars AND the CSR
    cudaStreamWaitEvent(0, evJ, 0);
    k_agg1<<<N_NODES, 128>>>(b1);
    k_l2<<<N_NODES, 128>>>(W2, as2, ad2);
    k_agg2<<<(N_NODES + 3) / 4, 128>>>(b2, out);
}